// round 9
// baseline (speedup 1.0000x reference)
#include <cuda_runtime.h>
#include <cuda_bf16.h>
#include <math.h>
#include <stdint.h>

// ---------------------------------------------------------------------------
// Problem constants
// ---------------------------------------------------------------------------
#define BATCH 4
#define SEQ   2048
#define EMB   1024
#define HEADS 16
#define HDIM  64
#define WIN   17
#define ROWS  (BATCH * SEQ)          // 8192
#define SCALE 0.125f
#define MAX_DIST 8.0f
#define MASK_PENALTY 10000.0f
#define KDIM  1024

// ---------------------------------------------------------------------------
// Scratch (static device globals; no allocation allowed)
// ---------------------------------------------------------------------------
__device__ float g_yq [ROWS * EMB];        // silu(x@Wq), RAW (LN fused into attention)
__device__ float g_ykv[ROWS * 2 * EMB];    // silu(x@Wkv), RAW k + v
__device__ float g_ws [ROWS * 32];

__device__ __nv_bfloat16 g_xhi[ROWS * EMB];
__device__ __nv_bfloat16 g_xlo[ROWS * EMB];
__device__ __nv_bfloat16 g_aohi[ROWS * EMB];
__device__ __nv_bfloat16 g_aolo[ROWS * EMB];

__device__ __nv_bfloat16 g_wfhi[3 * EMB * KDIM];   // [Wq | Wkv]^T
__device__ __nv_bfloat16 g_wflo[3 * EMB * KDIM];
__device__ __nv_bfloat16 g_wothi[EMB * KDIM];      // Wout^T
__device__ __nv_bfloat16 g_wotlo[EMB * KDIM];

__device__ __forceinline__ float sigmoidf_(float x) { return 1.0f / (1.0f + expf(-x)); }
__device__ __forceinline__ float siluf_(float x)    { return x / (1.0f + expf(-x)); }

__device__ __forceinline__ uint32_t smem_u32(const void* p) {
    uint32_t a;
    asm("{ .reg .u64 t; cvta.to.shared.u64 t, %1; cvt.u32.u64 %0, t; }" : "=r"(a) : "l"(p));
    return a;
}

#define CP_ASYNC16(dst, src) \
    asm volatile("cp.async.cg.shared.global [%0], [%1], 16;" :: "r"(dst), "l"(src) : "memory")
#define CP_COMMIT() asm volatile("cp.async.commit_group;" ::: "memory")
#define CP_WAIT(n)  asm volatile("cp.async.wait_group %0;" :: "n"(n) : "memory")

__device__ __forceinline__ void ldmx4(uint32_t* r, uint32_t addr) {
    asm volatile("ldmatrix.sync.aligned.m8n8.x4.shared.b16 {%0,%1,%2,%3}, [%4];"
                 : "=r"(r[0]), "=r"(r[1]), "=r"(r[2]), "=r"(r[3]) : "r"(addr));
}
__device__ __forceinline__ void mma16816(float* d, const uint32_t* a, const uint32_t* b) {
    asm volatile(
        "mma.sync.aligned.m16n8k16.row.col.f32.bf16.bf16.f32 "
        "{%0,%1,%2,%3}, {%4,%5,%6,%7}, {%8,%9}, {%0,%1,%2,%3};"
        : "+f"(d[0]), "+f"(d[1]), "+f"(d[2]), "+f"(d[3])
        : "r"(a[0]), "r"(a[1]), "r"(a[2]), "r"(a[3]), "r"(b[0]), "r"(b[1]));
}

// ---------------------------------------------------------------------------
// Split-bf16 tensor-core GEMM: CTA 128x128x32, 256 threads, 8 warps (2x4),
// warp tile 64x32, 3-stage cp.async pipeline.
// B fragments loaded with ldmatrix.x4 (2 n-tiles per op).
// ---------------------------------------------------------------------------
#define BK        32
#define ROW_PITCH 80
#define MAT_BYTES (128 * ROW_PITCH)
#define STAGE_B   (4 * MAT_BYTES)        // 40960
#define NSTAGE    3
#define SMEM_GEMM (NSTAGE * STAGE_B)     // 122880

__device__ __forceinline__ void load_stage_mm(
    uint32_t stage, const __nv_bfloat16* Ah, const __nv_bfloat16* Al,
    const __nv_bfloat16* Bh, const __nv_bfloat16* Bl,
    int m0, int n0, int k0, int tid)
{
    #pragma unroll
    for (int j = 0; j < 8; j++) {
        const int g   = tid + j * 256;      // 0..2047
        const int mat = g >> 9;
        const int rem = g & 511;
        const int row = rem >> 2;
        const int c   = rem & 3;
        const uint32_t dst = stage + mat * MAT_BYTES + row * ROW_PITCH + c * 16;
        const __nv_bfloat16* src;
        if (mat == 0)      src = Ah + (size_t)(m0 + row) * KDIM + k0 + c * 8;
        else if (mat == 1) src = Al + (size_t)(m0 + row) * KDIM + k0 + c * 8;
        else if (mat == 2) src = Bh + (size_t)(n0 + row) * KDIM + k0 + c * 8;
        else               src = Bl + (size_t)(n0 + row) * KDIM + k0 + c * 8;
        CP_ASYNC16(dst, src);
    }
}

__global__ __launch_bounds__(256, 1) void gemm_mm_kernel(
    const __nv_bfloat16* __restrict__ Ah, const __nv_bfloat16* __restrict__ Al,
    const __nv_bfloat16* __restrict__ Bh, const __nv_bfloat16* __restrict__ Bl,
    float* __restrict__ C1, int ldc1, float* __restrict__ C2, int ldc2, int ncut)
{
    extern __shared__ char smem[];
    const uint32_t sb = smem_u32(smem);

    const int tid  = threadIdx.x;
    const int wid  = tid >> 5;
    const int lane = tid & 31;
    const int wm   = wid >> 2;       // 0..1 (64-row slab)
    const int wn   = wid & 3;        // 0..3 (32-col slab)
    const int m0   = blockIdx.y * 128;
    const int n0   = blockIdx.x * 128;

    float acc[4][4][4];
    #pragma unroll
    for (int f = 0; f < 4; f++)
        #pragma unroll
        for (int g = 0; g < 4; g++)
            #pragma unroll
            for (int c = 0; c < 4; c++) acc[f][g][c] = 0.0f;

    const int NCH = KDIM / BK;   // 32

    load_stage_mm(sb + 0 * STAGE_B, Ah, Al, Bh, Bl, m0, n0, 0,  tid); CP_COMMIT();
    load_stage_mm(sb + 1 * STAGE_B, Ah, Al, Bh, Bl, m0, n0, BK, tid); CP_COMMIT();

    // A frag addressing: lanes 0-15 -> rows of the 16-row tile, lane>>4 -> 16B k-half
    const uint32_t arow = (uint32_t)(lane & 15);
    const uint32_t achk = (uint32_t)(lane >> 4);
    // B frag addressing for x4 (2 n-tiles per op)
    const uint32_t brow8 = (uint32_t)(lane & 7);
    const uint32_t bgk   = (uint32_t)((lane >> 3) & 1);
    const uint32_t bgg   = (uint32_t)(lane >> 4);

    for (int i = 0; i < NCH; i++) {
        if (i < NCH - 1) { CP_WAIT(1); } else { CP_WAIT(0); }
        __syncthreads();

        // issue next stage's gmem loads first: overlap with LDSM + MMA below
        if (i + 2 < NCH) {
            load_stage_mm(sb + (uint32_t)((i + 2) % NSTAGE) * STAGE_B,
                          Ah, Al, Bh, Bl, m0, n0, (i + 2) * BK, tid);
            CP_COMMIT();
        }

        const uint32_t stage = sb + (uint32_t)(i % NSTAGE) * STAGE_B;
        const uint32_t sAh = stage;
        const uint32_t sAl = stage + MAT_BYTES;
        const uint32_t sBh = stage + 2 * MAT_BYTES;
        const uint32_t sBl = stage + 3 * MAT_BYTES;

        #pragma unroll
        for (int s = 0; s < 2; s++) {
            uint32_t aH[4][4], aL[4][4], bH[4][2], bL[4][2];
            #pragma unroll
            for (int f = 0; f < 4; f++) {
                const uint32_t off = (uint32_t)(wm * 64 + f * 16 + arow) * ROW_PITCH
                                   + (2 * s + achk) * 16;
                ldmx4(aH[f], sAh + off);
                ldmx4(aL[f], sAl + off);
            }
            #pragma unroll
            for (int gp = 0; gp < 2; gp++) {
                const uint32_t off =
                    (uint32_t)(wn * 32 + (2 * gp + bgg) * 8 + brow8) * ROW_PITCH
                    + (2 * s + bgk) * 16;
                ldmx4(&bH[2 * gp][0], sBh + off);   // fills bH[2gp], bH[2gp+1]
                ldmx4(&bL[2 * gp][0], sBl + off);
            }
            #pragma unroll
            for (int f = 0; f < 4; f++)
                #pragma unroll
                for (int g = 0; g < 4; g++) mma16816(acc[f][g], aH[f], bH[g]);
            #pragma unroll
            for (int f = 0; f < 4; f++)
                #pragma unroll
                for (int g = 0; g < 4; g++) mma16816(acc[f][g], aH[f], bL[g]);
            #pragma unroll
            for (int f = 0; f < 4; f++)
                #pragma unroll
                for (int g = 0; g < 4; g++) mma16816(acc[f][g], aL[f], bH[g]);
        }
    }

    // epilogue: silu + fp32 store, routed by n0 (uniform per block)
    float* Cb; int ldc, nbase;
    if (n0 < ncut) { Cb = C1; ldc = ldc1; nbase = n0; }
    else           { Cb = C2; ldc = ldc2; nbase = n0 - ncut; }

    const int rlo  = m0 + wm * 64 + (lane >> 2);
    const int col0 = nbase + wn * 32 + 2 * (lane & 3);
    #pragma unroll
    for (int f = 0; f < 4; f++) {
        #pragma unroll
        for (int g = 0; g < 4; g++) {
            float2 v0, v1;
            v0.x = siluf_(acc[f][g][0]);
            v0.y = siluf_(acc[f][g][1]);
            v1.x = siluf_(acc[f][g][2]);
            v1.y = siluf_(acc[f][g][3]);
            const int col = col0 + g * 8;
            *(float2*)(Cb + (size_t)(rlo + f * 16)     * ldc + col) = v0;
            *(float2*)(Cb + (size_t)(rlo + f * 16 + 8) * ldc + col) = v1;
        }
    }
}

// ---------------------------------------------------------------------------
// x -> hi/lo bf16 split
// ---------------------------------------------------------------------------
__global__ __launch_bounds__(256) void split_kernel(
    const float* __restrict__ src, __nv_bfloat16* __restrict__ hi,
    __nv_bfloat16* __restrict__ lo, int n4)
{
    const int i = blockIdx.x * 256 + threadIdx.x;
    if (i >= n4) return;
    float4 v = ((const float4*)src)[i];
    __nv_bfloat16 hx = __float2bfloat16(v.x), hy = __float2bfloat16(v.y);
    __nv_bfloat16 hz = __float2bfloat16(v.z), hw = __float2bfloat16(v.w);
    __nv_bfloat162* H = (__nv_bfloat162*)hi;
    __nv_bfloat162* L = (__nv_bfloat162*)lo;
    H[i * 2 + 0] = __nv_bfloat162(hx, hy);
    H[i * 2 + 1] = __nv_bfloat162(hz, hw);
    L[i * 2 + 0] = __nv_bfloat162(__float2bfloat16(v.x - __bfloat162float(hx)),
                                  __float2bfloat16(v.y - __bfloat162float(hy)));
    L[i * 2 + 1] = __nv_bfloat162(__float2bfloat16(v.z - __bfloat162float(hz)),
                                  __float2bfloat16(v.w - __bfloat162float(hw)));
}

// ---------------------------------------------------------------------------
// W [K x N] fp32 -> W^T hi/lo bf16 [N x K]
// ---------------------------------------------------------------------------
__global__ __launch_bounds__(256) void wsplit_kernel(
    const float* __restrict__ W, __nv_bfloat16* __restrict__ Thi,
    __nv_bfloat16* __restrict__ Tlo, int K, int N)
{
    __shared__ float t[32][33];
    const int n0 = blockIdx.x * 32, k0 = blockIdx.y * 32;
    const int tx = threadIdx.x & 31, ty = threadIdx.x >> 5;
    #pragma unroll
    for (int j = 0; j < 4; j++)
        t[ty + 8 * j][tx] = W[(size_t)(k0 + ty + 8 * j) * N + n0 + tx];
    __syncthreads();
    #pragma unroll
    for (int j = 0; j < 4; j++) {
        const float v = t[tx][ty + 8 * j];
        const size_t o = (size_t)(n0 + ty + 8 * j) * K + k0 + tx;
        __nv_bfloat16 h = __float2bfloat16(v);
        Thi[o] = h;
        Tlo[o] = __float2bfloat16(v - __bfloat162float(h));
    }
}

// ---------------------------------------------------------------------------
// Win projection
// ---------------------------------------------------------------------------
__global__ __launch_bounds__(256) void win_kernel(
    const float* __restrict__ x, const float* __restrict__ Wwin,
    const float* __restrict__ bwin, float* __restrict__ ws)
{
    __shared__ float sx[EMB];
    __shared__ float red[256];
    const int row = blockIdx.x;
    const int tid = threadIdx.x;

    *(float4*)&sx[tid * 4] = *(const float4*)(x + (size_t)row * EMB + tid * 4);
    __syncthreads();

    const int j = tid & 31;
    const int chunk = tid >> 5;
    float acc = 0.0f;
    const int kbeg = chunk * 128;
    #pragma unroll 4
    for (int k = kbeg; k < kbeg + 128; k++)
        acc = fmaf(sx[k], Wwin[(size_t)k * 32 + j], acc);
    red[tid] = acc;
    __syncthreads();

    if (tid < 32) {
        float s = 0.0f;
        #pragma unroll
        for (int c = 0; c < 8; c++) s += red[c * 32 + tid];
        float wp = siluf_(s + bwin[tid]);
        float out;
        if (tid < 16) out = sigmoidf_(wp) * MAX_DIST + 0.5f;
        else          out = sigmoidf_(wp) * 9.5f + 0.5f;
        ws[(size_t)row * 32 + tid] = out;
    }
}

// ---------------------------------------------------------------------------
// Smem-tiled local-window attention with FUSED q/k LayerNorm.
// ---------------------------------------------------------------------------
#define TL      256
#define KROWS   (TL + 16)     // 272
#define KPITCH  274
#define OPITCH  257
#define SMEM_ATT (2 * 64 * KPITCH * 4)   // 140288 B

__global__ __launch_bounds__(256, 1) void attn_kernel(
    const float* __restrict__ q_g, const float* __restrict__ q_b,
    const float* __restrict__ k_g, const float* __restrict__ k_b)
{
    extern __shared__ float sm[];
    float* k_s = sm;
    float* v_s = sm + 64 * KPITCH;

    const int tid = threadIdx.x;
    const int l0  = blockIdx.x * TL;
    const int h   = blockIdx.y;
    const int b   = blockIdx.z;

    const size_t kvbase = (size_t)b * SEQ * (2 * EMB) + h * HDIM;
    for (int idx = tid; idx < KROWS * 16; idx += 256) {
        const int row = idx >> 4;
        const int c4  = idx & 15;
        const int pos = l0 - 8 + row;
        float4 kv4 = make_float4(0.f, 0.f, 0.f, 0.f);
        float4 vv4 = make_float4(0.f, 0.f, 0.f, 0.f);
        if (pos >= 0 && pos < SEQ) {
            const float* base = g_ykv + kvbase + (size_t)pos * (2 * EMB);
            kv4 = *(const float4*)(base + c4 * 4);
            vv4 = *(const float4*)(base + EMB + c4 * 4);
        }
        const int d0 = c4 * 4;
        k_s[(d0 + 0) * KPITCH + row] = kv4.x;
        k_s[(d0 + 1) * KPITCH + row] = kv4.y;
        k_s[(d0 + 2) * KPITCH + row] = kv4.z;
        k_s[(d0 + 3) * KPITCH + row] = kv4.w;
        v_s[(d0 + 0) * KPITCH + row] = vv4.x;
        v_s[(d0 + 1) * KPITCH + row] = vv4.y;
        v_s[(d0 + 2) * KPITCH + row] = vv4.z;
        v_s[(d0 + 3) * KPITCH + row] = vv4.w;
    }
    __syncthreads();

    // fused k LayerNorm over staged slab (valid rows only; OOB stays zero)
    for (int row = tid; row < KROWS; row += 256) {
        const int pos = l0 - 8 + row;
        if (pos >= 0 && pos < SEQ) {
            float s = 0.f, sq = 0.f;
            #pragma unroll 8
            for (int d = 0; d < 64; d++) {
                const float v = k_s[d * KPITCH + row];
                s += v; sq += v * v;
            }
            const float mu  = s * (1.0f / 64.0f);
            const float var = sq * (1.0f / 64.0f) - mu * mu;
            const float rs  = rsqrtf(var + 1e-5f);
            #pragma unroll 8
            for (int d = 0; d < 64; d++) {
                const float v = k_s[d * KPITCH + row];
                k_s[d * KPITCH + row] = (v - mu) * rs * k_g[d] + k_b[d];
            }
        }
    }
    __syncthreads();

    float sc0[WIN], sc1[WIN];
    const int t = tid;
    if (t < 128) {
        const int p0 = 2 * t;
        const int rg0 = b * SEQ + l0 + p0;
        const float* q0 = g_yq + (size_t)rg0 * EMB + h * HDIM;
        const float* q1 = q0 + EMB;

        float a0 = 0.f, v0a = 0.f, a1 = 0.f, v1a = 0.f;
        #pragma unroll 8
        for (int d = 0; d < 64; d++) {
            const float u0 = q0[d], u1 = q1[d];
            a0 += u0; v0a += u0 * u0;
            a1 += u1; v1a += u1 * u1;
        }
        const float mu0 = a0 * (1.0f / 64.0f);
        const float rs0 = rsqrtf(v0a * (1.0f / 64.0f) - mu0 * mu0 + 1e-5f);
        const float mu1 = a1 * (1.0f / 64.0f);
        const float rs1 = rsqrtf(v1a * (1.0f / 64.0f) - mu1 * mu1 + 1e-5f);

        #pragma unroll
        for (int w = 0; w < WIN; w++) { sc0[w] = 0.f; sc1[w] = 0.f; }

        for (int d = 0; d < 64; d++) {
            const float gd = q_g[d], bd = q_b[d];
            const float q0d = (q0[d] - mu0) * rs0 * gd + bd;
            const float q1d = (q1[d] - mu1) * rs1 * gd + bd;
            const float* kc = k_s + d * KPITCH + p0;
            float ka[18];
            #pragma unroll
            for (int j = 0; j < 9; j++) {
                float2 f2 = *(const float2*)(kc + 2 * j);
                ka[2 * j] = f2.x; ka[2 * j + 1] = f2.y;
            }
            #pragma unroll
            for (int w = 0; w < WIN; w++) {
                sc0[w] = fmaf(q0d, ka[w],     sc0[w]);
                sc1[w] = fmaf(q1d, ka[w + 1], sc1[w]);
            }
        }

        const float wd0 = g_ws[(size_t)rg0 * 32 + h];
        const float sh0 = g_ws[(size_t)rg0 * 32 + 16 + h];
        const float wd1 = g_ws[(size_t)(rg0 + 1) * 32 + h];
        const float sh1 = g_ws[(size_t)(rg0 + 1) * 32 + 16 + h];
        #pragma unroll
        for (int w = 0; w < WIN; w++) {
            const float rel = fabsf((float)w - 8.0f);
            sc0[w] = sc0[w] * SCALE - (1.0f - sigmoidf_((wd0 - rel) * sh0)) * MASK_PENALTY;
            sc1[w] = sc1[w] * SCALE - (1.0f - sigmoidf_((wd1 - rel) * sh1)) * MASK_PENALTY;
        }
        float m0 = sc0[0], m1 = sc1[0];
        #pragma unroll
        for (int w = 1; w < WIN; w++) { m0 = fmaxf(m0, sc0[w]); m1 = fmaxf(m1, sc1[w]); }
        float s0 = 0.f, s1 = 0.f;
        #pragma unroll
        for (int w = 0; w < WIN; w++) {
            sc0[w] = expf(sc0[w] - m0); s0 += sc0[w];
            sc1[w] = expf(sc1[w] - m1); s1 += sc1[w];
        }
        const float i0 = 1.0f / s0, i1 = 1.0f / s1;
        #pragma unroll
        for (int w = 0; w < WIN; w++) { sc0[w] *= i0; sc1[w] *= i1; }
    }
    __syncthreads();

    float* o_s = k_s;
    if (t < 128) {
        const int p0 = 2 * t;
        for (int d = 0; d < 64; d++) {
            const float* vc = v_s + d * KPITCH + p0;
            float va[18];
            #pragma unroll
            for (int j = 0; j < 9; j++) {
                float2 f2 = *(const float2*)(vc + 2 * j);
                va[2 * j] = f2.x; va[2 * j + 1] = f2.y;
            }
            float o0 = 0.f, o1 = 0.f;
            #pragma unroll
            for (int w = 0; w < WIN; w++) {
                o0 = fmaf(sc0[w], va[w],     o0);
                o1 = fmaf(sc1[w], va[w + 1], o1);
            }
            o_s[d * OPITCH + p0]     = o0;
            o_s[d * OPITCH + p0 + 1] = o1;
        }
    }
    __syncthreads();

    const int wid  = tid >> 5;
    const int lane = tid & 31;
    #pragma unroll
    for (int i = 0; i < 32; i++) {
        const int row = wid * 32 + i;
        const int rg  = b * SEQ + l0 + row;
        const float f0 = o_s[(2 * lane)     * OPITCH + row];
        const float f1 = o_s[(2 * lane + 1) * OPITCH + row];
        const __nv_bfloat16 h0 = __float2bfloat16(f0);
        const __nv_bfloat16 h1 = __float2bfloat16(f1);
        const size_t o = (size_t)rg * EMB + h * HDIM + 2 * lane;
        *(__nv_bfloat162*)(g_aohi + o) = __nv_bfloat162(h0, h1);
        *(__nv_bfloat162*)(g_aolo + o) =
            __nv_bfloat162(__float2bfloat16(f0 - __bfloat162float(h0)),
                           __float2bfloat16(f1 - __bfloat162float(h1)));
    }
}

// ---------------------------------------------------------------------------
// Launch — metadata order: x, Wq, Wkv, q_g, q_b, k_g, k_b, Wwin, bwin, Wout
// ---------------------------------------------------------------------------
extern "C" void kernel_launch(void* const* d_in, const int* in_sizes, int n_in,
                              void* d_out, int out_size)
{
    const float* x    = (const float*)d_in[0];
    const float* Wq   = (const float*)d_in[1];
    const float* Wkv  = (const float*)d_in[2];
    const float* q_g  = (const float*)d_in[3];
    const float* q_b  = (const float*)d_in[4];
    const float* k_g  = (const float*)d_in[5];
    const float* k_b  = (const float*)d_in[6];
    const float* Wwin = (const float*)d_in[7];
    const float* bwin = (const float*)d_in[8];
    const float* Wout = (const float*)d_in[9];
    float* out = (float*)d_out;

    float* yq;    cudaGetSymbolAddress((void**)&yq,    g_yq);
    float* ykv;   cudaGetSymbolAddress((void**)&ykv,   g_ykv);
    float* ws;    cudaGetSymbolAddress((void**)&ws,    g_ws);
    __nv_bfloat16 *xhi, *xlo, *aohi, *aolo, *wfh, *wfl, *woh, *wol;
    cudaGetSymbolAddress((void**)&xhi,  g_xhi);
    cudaGetSymbolAddress((void**)&xlo,  g_xlo);
    cudaGetSymbolAddress((void**)&aohi, g_aohi);
    cudaGetSymbolAddress((void**)&aolo, g_aolo);
    cudaGetSymbolAddress((void**)&wfh,  g_wfhi);
    cudaGetSymbolAddress((void**)&wfl,  g_wflo);
    cudaGetSymbolAddress((void**)&woh,  g_wothi);
    cudaGetSymbolAddress((void**)&wol,  g_wotlo);

    cudaFuncSetAttribute(gemm_mm_kernel, cudaFuncAttributeMaxDynamicSharedMemorySize, SMEM_GEMM);
    cudaFuncSetAttribute(attn_kernel,    cudaFuncAttributeMaxDynamicSharedMemorySize, SMEM_ATT);

    // 0) precision-split inputs; fused [Wq | Wkv]^T and Wout^T
    split_kernel<<<(ROWS * EMB / 4 + 255) / 256, 256>>>(x, xhi, xlo, ROWS * EMB / 4);
    wsplit_kernel<<<dim3(EMB / 32,     KDIM / 32), 256>>>(Wq,   wfh,              wfl,              KDIM, EMB);
    wsplit_kernel<<<dim3(2 * EMB / 32, KDIM / 32), 256>>>(Wkv,  wfh + EMB * KDIM, wfl + EMB * KDIM, KDIM, 2 * EMB);
    wsplit_kernel<<<dim3(EMB / 32,     KDIM / 32), 256>>>(Wout, woh,              wol,              KDIM, EMB);

    // 1) fused: [yq | ykv] = silu(x @ [Wq | Wkv])   (RAW; LN fused into attention)
    gemm_mm_kernel<<<dim3(3 * EMB / 128, ROWS / 128), 256, SMEM_GEMM>>>(
        xhi, xlo, wfh, wfl, yq, EMB, ykv, 2 * EMB, EMB);
    // 2) width/sharp
    win_kernel<<<ROWS, 256>>>(x, Wwin, bwin, ws);
    // 3) attention (fused q/k LN) -> split bf16 ao
    attn_kernel<<<dim3(SEQ / TL, HEADS, BATCH), 256, SMEM_ATT>>>(q_g, q_b, k_g, k_b);
    // 4) out = silu(ao @ Wout)
    gemm_mm_kernel<<<dim3(EMB / 128, ROWS / 128), 256, SMEM_GEMM>>>(
        aohi, aolo, woh, wol, out, EMB, out, EMB, EMB);
}

// round 10
// speedup vs baseline: 1.0813x; 1.0813x over previous
#include <cuda_runtime.h>
#include <cuda_bf16.h>
#include <math.h>
#include <stdint.h>

// ---------------------------------------------------------------------------
// Problem constants
// ---------------------------------------------------------------------------
#define BATCH 4
#define SEQ   2048
#define EMB   1024
#define HEADS 16
#define HDIM  64
#define WIN   17
#define ROWS  (BATCH * SEQ)          // 8192
#define SCALE 0.125f
#define MAX_DIST 8.0f
#define MASK_PENALTY 10000.0f
#define KDIM  1024

// ---------------------------------------------------------------------------
// Scratch (static device globals; no allocation allowed)
// ---------------------------------------------------------------------------
__device__ float g_yq [ROWS * EMB];        // silu(x@Wq), RAW (LN fused into attention)
__device__ float g_ykv[ROWS * 2 * EMB];    // silu(x@Wkv), RAW k + v
__device__ float g_ws [ROWS * 32];

__device__ __nv_bfloat16 g_xhi[ROWS * EMB];
__device__ __nv_bfloat16 g_xlo[ROWS * EMB];
__device__ __nv_bfloat16 g_aohi[ROWS * EMB];
__device__ __nv_bfloat16 g_aolo[ROWS * EMB];

__device__ __nv_bfloat16 g_wfhi[3 * EMB * KDIM];   // [Wq | Wkv]^T
__device__ __nv_bfloat16 g_wflo[3 * EMB * KDIM];
__device__ __nv_bfloat16 g_wothi[EMB * KDIM];      // Wout^T
__device__ __nv_bfloat16 g_wotlo[EMB * KDIM];

__device__ __forceinline__ float sigmoidf_(float x) { return 1.0f / (1.0f + expf(-x)); }
__device__ __forceinline__ float siluf_(float x)    { return x / (1.0f + expf(-x)); }

__device__ __forceinline__ uint32_t smem_u32(const void* p) {
    uint32_t a;
    asm("{ .reg .u64 t; cvta.to.shared.u64 t, %1; cvt.u32.u64 %0, t; }" : "=r"(a) : "l"(p));
    return a;
}

#define CP_ASYNC16(dst, src) \
    asm volatile("cp.async.cg.shared.global [%0], [%1], 16;" :: "r"(dst), "l"(src) : "memory")
#define CP_COMMIT() asm volatile("cp.async.commit_group;" ::: "memory")
#define CP_WAIT(n)  asm volatile("cp.async.wait_group %0;" :: "n"(n) : "memory")

__device__ __forceinline__ void ldmx4(uint32_t* r, uint32_t addr) {
    asm volatile("ldmatrix.sync.aligned.m8n8.x4.shared.b16 {%0,%1,%2,%3}, [%4];"
                 : "=r"(r[0]), "=r"(r[1]), "=r"(r[2]), "=r"(r[3]) : "r"(addr));
}
__device__ __forceinline__ void ldmx2(uint32_t* r, uint32_t addr) {
    asm volatile("ldmatrix.sync.aligned.m8n8.x2.shared.b16 {%0,%1}, [%2];"
                 : "=r"(r[0]), "=r"(r[1]) : "r"(addr));
}
__device__ __forceinline__ void mma16816(float* d, const uint32_t* a, const uint32_t* b) {
    asm volatile(
        "mma.sync.aligned.m16n8k16.row.col.f32.bf16.bf16.f32 "
        "{%0,%1,%2,%3}, {%4,%5,%6,%7}, {%8,%9}, {%0,%1,%2,%3};"
        : "+f"(d[0]), "+f"(d[1]), "+f"(d[2]), "+f"(d[3])
        : "r"(a[0]), "r"(a[1]), "r"(a[2]), "r"(a[3]), "r"(b[0]), "r"(b[1]));
}

// ---------------------------------------------------------------------------
// Split-bf16 tensor-core GEMM (R6-winning config): CTA 128x128x32, 256 threads,
// 8 warps (2x4), warp tile 64x32, ldmx4 A + ldmx2 B, 3-stage cp.async,
// next-stage load issued AFTER the MMA block.
// ---------------------------------------------------------------------------
#define BK        32
#define ROW_PITCH 80
#define MAT_BYTES (128 * ROW_PITCH)
#define STAGE_B   (4 * MAT_BYTES)        // 40960
#define NSTAGE    3
#define SMEM_GEMM (NSTAGE * STAGE_B)     // 122880

__device__ __forceinline__ void load_stage_mm(
    uint32_t stage, const __nv_bfloat16* Ah, const __nv_bfloat16* Al,
    const __nv_bfloat16* Bh, const __nv_bfloat16* Bl,
    int m0, int n0, int k0, int tid)
{
    #pragma unroll
    for (int j = 0; j < 8; j++) {
        const int g   = tid + j * 256;      // 0..2047
        const int mat = g >> 9;
        const int rem = g & 511;
        const int row = rem >> 2;
        const int c   = rem & 3;
        const uint32_t dst = stage + mat * MAT_BYTES + row * ROW_PITCH + c * 16;
        const __nv_bfloat16* src;
        if (mat == 0)      src = Ah + (size_t)(m0 + row) * KDIM + k0 + c * 8;
        else if (mat == 1) src = Al + (size_t)(m0 + row) * KDIM + k0 + c * 8;
        else if (mat == 2) src = Bh + (size_t)(n0 + row) * KDIM + k0 + c * 8;
        else               src = Bl + (size_t)(n0 + row) * KDIM + k0 + c * 8;
        CP_ASYNC16(dst, src);
    }
}

__global__ __launch_bounds__(256, 1) void gemm_mm_kernel(
    const __nv_bfloat16* __restrict__ Ah, const __nv_bfloat16* __restrict__ Al,
    const __nv_bfloat16* __restrict__ Bh, const __nv_bfloat16* __restrict__ Bl,
    float* __restrict__ C1, int ldc1, float* __restrict__ C2, int ldc2, int ncut)
{
    extern __shared__ char smem[];
    const uint32_t sb = smem_u32(smem);

    const int tid  = threadIdx.x;
    const int wid  = tid >> 5;
    const int lane = tid & 31;
    const int wm   = wid >> 2;       // 0..1
    const int wn   = wid & 3;        // 0..3
    const int m0   = blockIdx.y * 128;
    const int n0   = blockIdx.x * 128;

    float acc[4][4][4];
    #pragma unroll
    for (int f = 0; f < 4; f++)
        #pragma unroll
        for (int g = 0; g < 4; g++)
            #pragma unroll
            for (int c = 0; c < 4; c++) acc[f][g][c] = 0.0f;

    const int NCH = KDIM / BK;   // 32

    load_stage_mm(sb + 0 * STAGE_B, Ah, Al, Bh, Bl, m0, n0, 0,  tid); CP_COMMIT();
    load_stage_mm(sb + 1 * STAGE_B, Ah, Al, Bh, Bl, m0, n0, BK, tid); CP_COMMIT();

    const uint32_t arow = (uint32_t)(lane & 15);
    const uint32_t achk = (uint32_t)(lane >> 4);
    const uint32_t brow = (uint32_t)(lane & 7);
    const uint32_t bchk = (uint32_t)((lane >> 3) & 1);

    for (int i = 0; i < NCH; i++) {
        if (i < NCH - 1) { CP_WAIT(1); } else { CP_WAIT(0); }
        __syncthreads();

        const uint32_t stage = sb + (uint32_t)(i % NSTAGE) * STAGE_B;
        const uint32_t sAh = stage;
        const uint32_t sAl = stage + MAT_BYTES;
        const uint32_t sBh = stage + 2 * MAT_BYTES;
        const uint32_t sBl = stage + 3 * MAT_BYTES;

        #pragma unroll
        for (int s = 0; s < 2; s++) {
            uint32_t aH[4][4], aL[4][4], bH[4][2], bL[4][2];
            #pragma unroll
            for (int f = 0; f < 4; f++) {
                const uint32_t off = (uint32_t)(wm * 64 + f * 16 + arow) * ROW_PITCH
                                   + (2 * s + achk) * 16;
                ldmx4(aH[f], sAh + off);
                ldmx4(aL[f], sAl + off);
            }
            #pragma unroll
            for (int g = 0; g < 4; g++) {
                const uint32_t off = (uint32_t)(wn * 32 + g * 8 + brow) * ROW_PITCH
                                   + (2 * s + bchk) * 16;
                ldmx2(bH[g], sBh + off);
                ldmx2(bL[g], sBl + off);
            }
            #pragma unroll
            for (int f = 0; f < 4; f++)
                #pragma unroll
                for (int g = 0; g < 4; g++) mma16816(acc[f][g], aH[f], bH[g]);
            #pragma unroll
            for (int f = 0; f < 4; f++)
                #pragma unroll
                for (int g = 0; g < 4; g++) mma16816(acc[f][g], aH[f], bL[g]);
            #pragma unroll
            for (int f = 0; f < 4; f++)
                #pragma unroll
                for (int g = 0; g < 4; g++) mma16816(acc[f][g], aL[f], bH[g]);
        }

        if (i + 2 < NCH) {
            load_stage_mm(sb + (uint32_t)((i + 2) % NSTAGE) * STAGE_B,
                          Ah, Al, Bh, Bl, m0, n0, (i + 2) * BK, tid);
            CP_COMMIT();
        }
    }

    // epilogue: silu + fp32 store, routed by n0 (uniform per block)
    float* Cb; int ldc, nbase;
    if (n0 < ncut) { Cb = C1; ldc = ldc1; nbase = n0; }
    else           { Cb = C2; ldc = ldc2; nbase = n0 - ncut; }

    const int rlo  = m0 + wm * 64 + (lane >> 2);
    const int col0 = nbase + wn * 32 + 2 * (lane & 3);
    #pragma unroll
    for (int f = 0; f < 4; f++) {
        #pragma unroll
        for (int g = 0; g < 4; g++) {
            float2 v0, v1;
            v0.x = siluf_(acc[f][g][0]);
            v0.y = siluf_(acc[f][g][1]);
            v1.x = siluf_(acc[f][g][2]);
            v1.y = siluf_(acc[f][g][3]);
            const int col = col0 + g * 8;
            *(float2*)(Cb + (size_t)(rlo + f * 16)     * ldc + col) = v0;
            *(float2*)(Cb + (size_t)(rlo + f * 16 + 8) * ldc + col) = v1;
        }
    }
}

// ---------------------------------------------------------------------------
// x -> hi/lo bf16 split
// ---------------------------------------------------------------------------
__global__ __launch_bounds__(256) void split_kernel(
    const float* __restrict__ src, __nv_bfloat16* __restrict__ hi,
    __nv_bfloat16* __restrict__ lo, int n4)
{
    const int i = blockIdx.x * 256 + threadIdx.x;
    if (i >= n4) return;
    float4 v = ((const float4*)src)[i];
    __nv_bfloat16 hx = __float2bfloat16(v.x), hy = __float2bfloat16(v.y);
    __nv_bfloat16 hz = __float2bfloat16(v.z), hw = __float2bfloat16(v.w);
    __nv_bfloat162* H = (__nv_bfloat162*)hi;
    __nv_bfloat162* L = (__nv_bfloat162*)lo;
    H[i * 2 + 0] = __nv_bfloat162(hx, hy);
    H[i * 2 + 1] = __nv_bfloat162(hz, hw);
    L[i * 2 + 0] = __nv_bfloat162(__float2bfloat16(v.x - __bfloat162float(hx)),
                                  __float2bfloat16(v.y - __bfloat162float(hy)));
    L[i * 2 + 1] = __nv_bfloat162(__float2bfloat16(v.z - __bfloat162float(hz)),
                                  __float2bfloat16(v.w - __bfloat162float(hw)));
}

// ---------------------------------------------------------------------------
// W [K x N] fp32 -> W^T hi/lo bf16 [N x K]
// ---------------------------------------------------------------------------
__global__ __launch_bounds__(256) void wsplit_kernel(
    const float* __restrict__ W, __nv_bfloat16* __restrict__ Thi,
    __nv_bfloat16* __restrict__ Tlo, int K, int N)
{
    __shared__ float t[32][33];
    const int n0 = blockIdx.x * 32, k0 = blockIdx.y * 32;
    const int tx = threadIdx.x & 31, ty = threadIdx.x >> 5;
    #pragma unroll
    for (int j = 0; j < 4; j++)
        t[ty + 8 * j][tx] = W[(size_t)(k0 + ty + 8 * j) * N + n0 + tx];
    __syncthreads();
    #pragma unroll
    for (int j = 0; j < 4; j++) {
        const float v = t[tx][ty + 8 * j];
        const size_t o = (size_t)(n0 + ty + 8 * j) * K + k0 + tx;
        __nv_bfloat16 h = __float2bfloat16(v);
        Thi[o] = h;
        Tlo[o] = __float2bfloat16(v - __bfloat162float(h));
    }
}

// ---------------------------------------------------------------------------
// Win projection
// ---------------------------------------------------------------------------
__global__ __launch_bounds__(256) void win_kernel(
    const float* __restrict__ x, const float* __restrict__ Wwin,
    const float* __restrict__ bwin, float* __restrict__ ws)
{
    __shared__ float sx[EMB];
    __shared__ float red[256];
    const int row = blockIdx.x;
    const int tid = threadIdx.x;

    *(float4*)&sx[tid * 4] = *(const float4*)(x + (size_t)row * EMB + tid * 4);
    __syncthreads();

    const int j = tid & 31;
    const int chunk = tid >> 5;
    float acc = 0.0f;
    const int kbeg = chunk * 128;
    #pragma unroll 4
    for (int k = kbeg; k < kbeg + 128; k++)
        acc = fmaf(sx[k], Wwin[(size_t)k * 32 + j], acc);
    red[tid] = acc;
    __syncthreads();

    if (tid < 32) {
        float s = 0.0f;
        #pragma unroll
        for (int c = 0; c < 8; c++) s += red[c * 32 + tid];
        float wp = siluf_(s + bwin[tid]);
        float out;
        if (tid < 16) out = sigmoidf_(wp) * MAX_DIST + 0.5f;
        else          out = sigmoidf_(wp) * 9.5f + 0.5f;
        ws[(size_t)row * 32 + tid] = out;
    }
}

// ---------------------------------------------------------------------------
// Smem-tiled local-window attention with FUSED q/k LayerNorm.
// ---------------------------------------------------------------------------
#define TL      256
#define KROWS   (TL + 16)     // 272
#define KPITCH  274
#define OPITCH  257
#define SMEM_ATT (2 * 64 * KPITCH * 4)   // 140288 B

__global__ __launch_bounds__(256, 1) void attn_kernel(
    const float* __restrict__ q_g, const float* __restrict__ q_b,
    const float* __restrict__ k_g, const float* __restrict__ k_b)
{
    extern __shared__ float sm[];
    float* k_s = sm;
    float* v_s = sm + 64 * KPITCH;

    const int tid = threadIdx.x;
    const int l0  = blockIdx.x * TL;
    const int h   = blockIdx.y;
    const int b   = blockIdx.z;

    const size_t kvbase = (size_t)b * SEQ * (2 * EMB) + h * HDIM;
    for (int idx = tid; idx < KROWS * 16; idx += 256) {
        const int row = idx >> 4;
        const int c4  = idx & 15;
        const int pos = l0 - 8 + row;
        float4 kv4 = make_float4(0.f, 0.f, 0.f, 0.f);
        float4 vv4 = make_float4(0.f, 0.f, 0.f, 0.f);
        if (pos >= 0 && pos < SEQ) {
            const float* base = g_ykv + kvbase + (size_t)pos * (2 * EMB);
            kv4 = *(const float4*)(base + c4 * 4);
            vv4 = *(const float4*)(base + EMB + c4 * 4);
        }
        const int d0 = c4 * 4;
        k_s[(d0 + 0) * KPITCH + row] = kv4.x;
        k_s[(d0 + 1) * KPITCH + row] = kv4.y;
        k_s[(d0 + 2) * KPITCH + row] = kv4.z;
        k_s[(d0 + 3) * KPITCH + row] = kv4.w;
        v_s[(d0 + 0) * KPITCH + row] = vv4.x;
        v_s[(d0 + 1) * KPITCH + row] = vv4.y;
        v_s[(d0 + 2) * KPITCH + row] = vv4.z;
        v_s[(d0 + 3) * KPITCH + row] = vv4.w;
    }
    __syncthreads();

    // fused k LayerNorm over staged slab (valid rows only; OOB stays zero)
    for (int row = tid; row < KROWS; row += 256) {
        const int pos = l0 - 8 + row;
        if (pos >= 0 && pos < SEQ) {
            float s = 0.f, sq = 0.f;
            #pragma unroll 8
            for (int d = 0; d < 64; d++) {
                const float v = k_s[d * KPITCH + row];
                s += v; sq += v * v;
            }
            const float mu  = s * (1.0f / 64.0f);
            const float var = sq * (1.0f / 64.0f) - mu * mu;
            const float rs  = rsqrtf(var + 1e-5f);
            #pragma unroll 8
            for (int d = 0; d < 64; d++) {
                const float v = k_s[d * KPITCH + row];
                k_s[d * KPITCH + row] = (v - mu) * rs * k_g[d] + k_b[d];
            }
        }
    }
    __syncthreads();

    float sc0[WIN], sc1[WIN];
    const int t = tid;
    if (t < 128) {
        const int p0 = 2 * t;
        const int rg0 = b * SEQ + l0 + p0;
        const float* q0 = g_yq + (size_t)rg0 * EMB + h * HDIM;
        const float* q1 = q0 + EMB;

        float a0 = 0.f, v0a = 0.f, a1 = 0.f, v1a = 0.f;
        #pragma unroll 8
        for (int d = 0; d < 64; d++) {
            const float u0 = q0[d], u1 = q1[d];
            a0 += u0; v0a += u0 * u0;
            a1 += u1; v1a += u1 * u1;
        }
        const float mu0 = a0 * (1.0f / 64.0f);
        const float rs0 = rsqrtf(v0a * (1.0f / 64.0f) - mu0 * mu0 + 1e-5f);
        const float mu1 = a1 * (1.0f / 64.0f);
        const float rs1 = rsqrtf(v1a * (1.0f / 64.0f) - mu1 * mu1 + 1e-5f);

        #pragma unroll
        for (int w = 0; w < WIN; w++) { sc0[w] = 0.f; sc1[w] = 0.f; }

        for (int d = 0; d < 64; d++) {
            const float gd = q_g[d], bd = q_b[d];
            const float q0d = (q0[d] - mu0) * rs0 * gd + bd;
            const float q1d = (q1[d] - mu1) * rs1 * gd + bd;
            const float* kc = k_s + d * KPITCH + p0;
            float ka[18];
            #pragma unroll
            for (int j = 0; j < 9; j++) {
                float2 f2 = *(const float2*)(kc + 2 * j);
                ka[2 * j] = f2.x; ka[2 * j + 1] = f2.y;
            }
            #pragma unroll
            for (int w = 0; w < WIN; w++) {
                sc0[w] = fmaf(q0d, ka[w],     sc0[w]);
                sc1[w] = fmaf(q1d, ka[w + 1], sc1[w]);
            }
        }

        const float wd0 = g_ws[(size_t)rg0 * 32 + h];
        const float sh0 = g_ws[(size_t)rg0 * 32 + 16 + h];
        const float wd1 = g_ws[(size_t)(rg0 + 1) * 32 + h];
        const float sh1 = g_ws[(size_t)(rg0 + 1) * 32 + 16 + h];
        #pragma unroll
        for (int w = 0; w < WIN; w++) {
            const float rel = fabsf((float)w - 8.0f);
            sc0[w] = sc0[w] * SCALE - (1.0f - sigmoidf_((wd0 - rel) * sh0)) * MASK_PENALTY;
            sc1[w] = sc1[w] * SCALE - (1.0f - sigmoidf_((wd1 - rel) * sh1)) * MASK_PENALTY;
        }
        float m0 = sc0[0], m1 = sc1[0];
        #pragma unroll
        for (int w = 1; w < WIN; w++) { m0 = fmaxf(m0, sc0[w]); m1 = fmaxf(m1, sc1[w]); }
        float s0 = 0.f, s1 = 0.f;
        #pragma unroll
        for (int w = 0; w < WIN; w++) {
            sc0[w] = expf(sc0[w] - m0); s0 += sc0[w];
            sc1[w] = expf(sc1[w] - m1); s1 += sc1[w];
        }
        const float i0 = 1.0f / s0, i1 = 1.0f / s1;
        #pragma unroll
        for (int w = 0; w < WIN; w++) { sc0[w] *= i0; sc1[w] *= i1; }
    }
    __syncthreads();

    float* o_s = k_s;
    if (t < 128) {
        const int p0 = 2 * t;
        for (int d = 0; d < 64; d++) {
            const float* vc = v_s + d * KPITCH + p0;
            float va[18];
            #pragma unroll
            for (int j = 0; j < 9; j++) {
                float2 f2 = *(const float2*)(vc + 2 * j);
                va[2 * j] = f2.x; va[2 * j + 1] = f2.y;
            }
            float o0 = 0.f, o1 = 0.f;
            #pragma unroll
            for (int w = 0; w < WIN; w++) {
                o0 = fmaf(sc0[w], va[w],     o0);
                o1 = fmaf(sc1[w], va[w + 1], o1);
            }
            o_s[d * OPITCH + p0]     = o0;
            o_s[d * OPITCH + p0 + 1] = o1;
        }
    }
    __syncthreads();

    const int wid  = tid >> 5;
    const int lane = tid & 31;
    #pragma unroll
    for (int i = 0; i < 32; i++) {
        const int row = wid * 32 + i;
        const int rg  = b * SEQ + l0 + row;
        const float f0 = o_s[(2 * lane)     * OPITCH + row];
        const float f1 = o_s[(2 * lane + 1) * OPITCH + row];
        const __nv_bfloat16 h0 = __float2bfloat16(f0);
        const __nv_bfloat16 h1 = __float2bfloat16(f1);
        const size_t o = (size_t)rg * EMB + h * HDIM + 2 * lane;
        *(__nv_bfloat162*)(g_aohi + o) = __nv_bfloat162(h0, h1);
        *(__nv_bfloat162*)(g_aolo + o) =
            __nv_bfloat162(__float2bfloat16(f0 - __bfloat162float(h0)),
                           __float2bfloat16(f1 - __bfloat162float(h1)));
    }
}

// ---------------------------------------------------------------------------
// Launch — metadata order: x, Wq, Wkv, q_g, q_b, k_g, k_b, Wwin, bwin, Wout
// ---------------------------------------------------------------------------
extern "C" void kernel_launch(void* const* d_in, const int* in_sizes, int n_in,
                              void* d_out, int out_size)
{
    const float* x    = (const float*)d_in[0];
    const float* Wq   = (const float*)d_in[1];
    const float* Wkv  = (const float*)d_in[2];
    const float* q_g  = (const float*)d_in[3];
    const float* q_b  = (const float*)d_in[4];
    const float* k_g  = (const float*)d_in[5];
    const float* k_b  = (const float*)d_in[6];
    const float* Wwin = (const float*)d_in[7];
    const float* bwin = (const float*)d_in[8];
    const float* Wout = (const float*)d_in[9];
    float* out = (float*)d_out;

    float* yq;    cudaGetSymbolAddress((void**)&yq,    g_yq);
    float* ykv;   cudaGetSymbolAddress((void**)&ykv,   g_ykv);
    float* ws;    cudaGetSymbolAddress((void**)&ws,    g_ws);
    __nv_bfloat16 *xhi, *xlo, *aohi, *aolo, *wfh, *wfl, *woh, *wol;
    cudaGetSymbolAddress((void**)&xhi,  g_xhi);
    cudaGetSymbolAddress((void**)&xlo,  g_xlo);
    cudaGetSymbolAddress((void**)&aohi, g_aohi);
    cudaGetSymbolAddress((void**)&aolo, g_aolo);
    cudaGetSymbolAddress((void**)&wfh,  g_wfhi);
    cudaGetSymbolAddress((void**)&wfl,  g_wflo);
    cudaGetSymbolAddress((void**)&woh,  g_wothi);
    cudaGetSymbolAddress((void**)&wol,  g_wotlo);

    cudaFuncSetAttribute(gemm_mm_kernel, cudaFuncAttributeMaxDynamicSharedMemorySize, SMEM_GEMM);
    cudaFuncSetAttribute(attn_kernel,    cudaFuncAttributeMaxDynamicSharedMemorySize, SMEM_ATT);

    // 0) precision-split inputs; fused [Wq | Wkv]^T and Wout^T
    split_kernel<<<(ROWS * EMB / 4 + 255) / 256, 256>>>(x, xhi, xlo, ROWS * EMB / 4);
    wsplit_kernel<<<dim3(EMB / 32,     KDIM / 32), 256>>>(Wq,   wfh,              wfl,              KDIM, EMB);
    wsplit_kernel<<<dim3(2 * EMB / 32, KDIM / 32), 256>>>(Wkv,  wfh + EMB * KDIM, wfl + EMB * KDIM, KDIM, 2 * EMB);
    wsplit_kernel<<<dim3(EMB / 32,     KDIM / 32), 256>>>(Wout, woh,              wol,              KDIM, EMB);

    // 1) fused: [yq | ykv] = silu(x @ [Wq | Wkv])   (RAW; LN fused into attention)
    gemm_mm_kernel<<<dim3(3 * EMB / 128, ROWS / 128), 256, SMEM_GEMM>>>(
        xhi, xlo, wfh, wfl, yq, EMB, ykv, 2 * EMB, EMB);
    // 2) width/sharp
    win_kernel<<<ROWS, 256>>>(x, Wwin, bwin, ws);
    // 3) attention (fused q/k LN) -> split bf16 ao
    attn_kernel<<<dim3(SEQ / TL, HEADS, BATCH), 256, SMEM_ATT>>>(q_g, q_b, k_g, k_b);
    // 4) out = silu(ao @ Wout)
    gemm_mm_kernel<<<dim3(EMB / 128, ROWS / 128), 256, SMEM_GEMM>>>(
        aohi, aolo, woh, wol, out, EMB, out, EMB, EMB);
}

// round 12
// speedup vs baseline: 1.1196x; 1.0354x over previous
#include <cuda_runtime.h>
#include <cuda_bf16.h>
#include <math.h>
#include <stdint.h>

// ---------------------------------------------------------------------------
// Problem constants
// ---------------------------------------------------------------------------
#define BATCH 4
#define SEQ   2048
#define EMB   1024
#define HEADS 16
#define HDIM  64
#define WIN   17
#define ROWS  (BATCH * SEQ)          // 8192
#define SCALE 0.125f
#define MAX_DIST 8.0f
#define MASK_PENALTY 10000.0f
#define KDIM  1024

// ---------------------------------------------------------------------------
// Scratch (static device globals; no allocation allowed)
// ---------------------------------------------------------------------------
__device__ float g_yq [ROWS * EMB];        // silu(x@Wq), RAW (LN fused into attention)
__device__ float g_ykv[ROWS * 2 * EMB];    // silu(x@Wkv), RAW k + v
__device__ float g_ws [ROWS * 32];

__device__ __nv_bfloat16 g_xhi[ROWS * EMB];
__device__ __nv_bfloat16 g_xlo[ROWS * EMB];
__device__ __nv_bfloat16 g_aohi[ROWS * EMB];
__device__ __nv_bfloat16 g_aolo[ROWS * EMB];

__device__ __nv_bfloat16 g_wfhi[3 * EMB * KDIM];   // [Wq | Wkv]^T
__device__ __nv_bfloat16 g_wflo[3 * EMB * KDIM];
__device__ __nv_bfloat16 g_wothi[EMB * KDIM];      // Wout^T
__device__ __nv_bfloat16 g_wotlo[EMB * KDIM];

__device__ __forceinline__ float sigmoidf_(float x) { return 1.0f / (1.0f + expf(-x)); }
__device__ __forceinline__ float siluf_(float x)    { return x / (1.0f + expf(-x)); }

__device__ __forceinline__ uint32_t smem_u32(const void* p) {
    uint32_t a;
    asm("{ .reg .u64 t; cvta.to.shared.u64 t, %1; cvt.u32.u64 %0, t; }" : "=r"(a) : "l"(p));
    return a;
}

#define CP_ASYNC16(dst, src) \
    asm volatile("cp.async.cg.shared.global [%0], [%1], 16;" :: "r"(dst), "l"(src) : "memory")
#define CP_COMMIT() asm volatile("cp.async.commit_group;" ::: "memory")
#define CP_WAIT(n)  asm volatile("cp.async.wait_group %0;" :: "n"(n) : "memory")

__device__ __forceinline__ void ldmx4(uint32_t* r, uint32_t addr) {
    asm volatile("ldmatrix.sync.aligned.m8n8.x4.shared.b16 {%0,%1,%2,%3}, [%4];"
                 : "=r"(r[0]), "=r"(r[1]), "=r"(r[2]), "=r"(r[3]) : "r"(addr));
}
__device__ __forceinline__ void ldmx2(uint32_t* r, uint32_t addr) {
    asm volatile("ldmatrix.sync.aligned.m8n8.x2.shared.b16 {%0,%1}, [%2];"
                 : "=r"(r[0]), "=r"(r[1]) : "r"(addr));
}
__device__ __forceinline__ void mma16816(float* d, const uint32_t* a, const uint32_t* b) {
    asm volatile(
        "mma.sync.aligned.m16n8k16.row.col.f32.bf16.bf16.f32 "
        "{%0,%1,%2,%3}, {%4,%5,%6,%7}, {%8,%9}, {%0,%1,%2,%3};"
        : "+f"(d[0]), "+f"(d[1]), "+f"(d[2]), "+f"(d[3])
        : "r"(a[0]), "r"(a[1]), "r"(a[2]), "r"(a[3]), "r"(b[0]), "r"(b[1]));
}

// ---------------------------------------------------------------------------
// Split-bf16 tensor-core GEMM (R8 measured-best config): CTA 128x128x32,
// 512 threads, 16 warps (4x4), warp tile 32x32, ldmx4 A + ldmx2 B,
// 5-stage cp.async pipeline, next-stage load issued AFTER the MMA block.
// ---------------------------------------------------------------------------
#define BK        32
#define ROW_PITCH 80
#define MAT_BYTES (128 * ROW_PITCH)
#define STAGE_B   (4 * MAT_BYTES)        // 40960
#define NSTAGE    5
#define SMEM_GEMM (NSTAGE * STAGE_B)     // 204800

__device__ __forceinline__ void load_stage_mm(
    uint32_t stage, const __nv_bfloat16* Ah, const __nv_bfloat16* Al,
    const __nv_bfloat16* Bh, const __nv_bfloat16* Bl,
    int m0, int n0, int k0, int tid)
{
    #pragma unroll
    for (int j = 0; j < 4; j++) {
        const int g   = tid + j * 512;      // 0..2047
        const int mat = g >> 9;
        const int rem = g & 511;
        const int row = rem >> 2;
        const int c   = rem & 3;
        const uint32_t dst = stage + mat * MAT_BYTES + row * ROW_PITCH + c * 16;
        const __nv_bfloat16* src;
        if (mat == 0)      src = Ah + (size_t)(m0 + row) * KDIM + k0 + c * 8;
        else if (mat == 1) src = Al + (size_t)(m0 + row) * KDIM + k0 + c * 8;
        else if (mat == 2) src = Bh + (size_t)(n0 + row) * KDIM + k0 + c * 8;
        else               src = Bl + (size_t)(n0 + row) * KDIM + k0 + c * 8;
        CP_ASYNC16(dst, src);
    }
}

__global__ __launch_bounds__(512, 1) void gemm_mm_kernel(
    const __nv_bfloat16* __restrict__ Ah, const __nv_bfloat16* __restrict__ Al,
    const __nv_bfloat16* __restrict__ Bh, const __nv_bfloat16* __restrict__ Bl,
    float* __restrict__ C1, int ldc1, float* __restrict__ C2, int ldc2, int ncut)
{
    extern __shared__ char smem[];
    const uint32_t sb = smem_u32(smem);

    const int tid  = threadIdx.x;
    const int wid  = tid >> 5;       // 0..15
    const int lane = tid & 31;
    const int wm   = wid >> 2;       // 0..3 (32-row slab)
    const int wn   = wid & 3;        // 0..3 (32-col slab)
    const int m0   = blockIdx.y * 128;
    const int n0   = blockIdx.x * 128;

    float acc[2][4][4];
    #pragma unroll
    for (int f = 0; f < 2; f++)
        #pragma unroll
        for (int g = 0; g < 4; g++)
            #pragma unroll
            for (int c = 0; c < 4; c++) acc[f][g][c] = 0.0f;

    const int NCH = KDIM / BK;   // 32

    // prologue: fill NSTAGE-1 = 4 stages
    load_stage_mm(sb + 0 * STAGE_B, Ah, Al, Bh, Bl, m0, n0, 0 * BK, tid); CP_COMMIT();
    load_stage_mm(sb + 1 * STAGE_B, Ah, Al, Bh, Bl, m0, n0, 1 * BK, tid); CP_COMMIT();
    load_stage_mm(sb + 2 * STAGE_B, Ah, Al, Bh, Bl, m0, n0, 2 * BK, tid); CP_COMMIT();
    load_stage_mm(sb + 3 * STAGE_B, Ah, Al, Bh, Bl, m0, n0, 3 * BK, tid); CP_COMMIT();

    const uint32_t arow = (uint32_t)(lane & 15);
    const uint32_t achk = (uint32_t)(lane >> 4);
    const uint32_t brow = (uint32_t)(lane & 7);
    const uint32_t bchk = (uint32_t)((lane >> 3) & 1);

    for (int i = 0; i < NCH; i++) {
        // committed chunks so far: min(NCH-1, i+3); need chunk i complete
        const int pend = (NCH - 1 < i + 3 ? NCH - 1 : i + 3) - i;
        if (pend >= 3)      { CP_WAIT(3); }
        else if (pend == 2) { CP_WAIT(2); }
        else if (pend == 1) { CP_WAIT(1); }
        else                { CP_WAIT(0); }
        __syncthreads();

        const uint32_t stage = sb + (uint32_t)(i % NSTAGE) * STAGE_B;
        const uint32_t sAh = stage;
        const uint32_t sAl = stage + MAT_BYTES;
        const uint32_t sBh = stage + 2 * MAT_BYTES;
        const uint32_t sBl = stage + 3 * MAT_BYTES;

        #pragma unroll
        for (int s = 0; s < 2; s++) {
            uint32_t aH[2][4], aL[2][4], bH[4][2], bL[4][2];
            #pragma unroll
            for (int f = 0; f < 2; f++) {
                const uint32_t off = (uint32_t)(wm * 32 + f * 16 + arow) * ROW_PITCH
                                   + (2 * s + achk) * 16;
                ldmx4(aH[f], sAh + off);
                ldmx4(aL[f], sAl + off);
            }
            #pragma unroll
            for (int g = 0; g < 4; g++) {
                const uint32_t off = (uint32_t)(wn * 32 + g * 8 + brow) * ROW_PITCH
                                   + (2 * s + bchk) * 16;
                ldmx2(bH[g], sBh + off);
                ldmx2(bL[g], sBl + off);
            }
            #pragma unroll
            for (int f = 0; f < 2; f++)
                #pragma unroll
                for (int g = 0; g < 4; g++) mma16816(acc[f][g], aH[f], bH[g]);
            #pragma unroll
            for (int f = 0; f < 2; f++)
                #pragma unroll
                for (int g = 0; g < 4; g++) mma16816(acc[f][g], aH[f], bL[g]);
            #pragma unroll
            for (int f = 0; f < 2; f++)
                #pragma unroll
                for (int g = 0; g < 4; g++) mma16816(acc[f][g], aL[f], bH[g]);
        }

        if (i + 4 < NCH) {
            load_stage_mm(sb + (uint32_t)((i + 4) % NSTAGE) * STAGE_B,
                          Ah, Al, Bh, Bl, m0, n0, (i + 4) * BK, tid);
            CP_COMMIT();
        }
    }

    // epilogue: silu + fp32 store, routed by n0 (uniform per block)
    float* Cb; int ldc, nbase;
    if (n0 < ncut) { Cb = C1; ldc = ldc1; nbase = n0; }
    else           { Cb = C2; ldc = ldc2; nbase = n0 - ncut; }

    const int rlo  = m0 + wm * 32 + (lane >> 2);
    const int col0 = nbase + wn * 32 + 2 * (lane & 3);
    #pragma unroll
    for (int f = 0; f < 2; f++) {
        #pragma unroll
        for (int g = 0; g < 4; g++) {
            float2 v0, v1;
            v0.x = siluf_(acc[f][g][0]);
            v0.y = siluf_(acc[f][g][1]);
            v1.x = siluf_(acc[f][g][2]);
            v1.y = siluf_(acc[f][g][3]);
            const int col = col0 + g * 8;
            *(float2*)(Cb + (size_t)(rlo + f * 16)     * ldc + col) = v0;
            *(float2*)(Cb + (size_t)(rlo + f * 16 + 8) * ldc + col) = v1;
        }
    }
}

// ---------------------------------------------------------------------------
// W [K x N] fp32 -> W^T hi/lo bf16 [N x K]
// ---------------------------------------------------------------------------
__global__ __launch_bounds__(256) void wsplit_kernel(
    const float* __restrict__ W, __nv_bfloat16* __restrict__ Thi,
    __nv_bfloat16* __restrict__ Tlo, int K, int N)
{
    __shared__ float t[32][33];
    const int n0 = blockIdx.x * 32, k0 = blockIdx.y * 32;
    const int tx = threadIdx.x & 31, ty = threadIdx.x >> 5;
    #pragma unroll
    for (int j = 0; j < 4; j++)
        t[ty + 8 * j][tx] = W[(size_t)(k0 + ty + 8 * j) * N + n0 + tx];
    __syncthreads();
    #pragma unroll
    for (int j = 0; j < 4; j++) {
        const float v = t[tx][ty + 8 * j];
        const size_t o = (size_t)(n0 + ty + 8 * j) * K + k0 + tx;
        __nv_bfloat16 h = __float2bfloat16(v);
        Thi[o] = h;
        Tlo[o] = __float2bfloat16(v - __bfloat162float(h));
    }
}

// ---------------------------------------------------------------------------
// Win projection + FUSED x -> hi/lo bf16 split (x row already in registers)
// ---------------------------------------------------------------------------
__global__ __launch_bounds__(256) void win_kernel(
    const float* __restrict__ x, const float* __restrict__ Wwin,
    const float* __restrict__ bwin, float* __restrict__ ws,
    __nv_bfloat16* __restrict__ xhi, __nv_bfloat16* __restrict__ xlo)
{
    __shared__ float sx[EMB];
    __shared__ float red[256];
    const int row = blockIdx.x;
    const int tid = threadIdx.x;

    const float4 v = *(const float4*)(x + (size_t)row * EMB + tid * 4);
    *(float4*)&sx[tid * 4] = v;

    // fused split: write hi/lo bf16 for these 4 elements
    {
        const __nv_bfloat16 hx = __float2bfloat16(v.x);
        const __nv_bfloat16 hy = __float2bfloat16(v.y);
        const __nv_bfloat16 hz = __float2bfloat16(v.z);
        const __nv_bfloat16 hw = __float2bfloat16(v.w);
        const size_t o = (size_t)row * EMB + tid * 4;
        *(__nv_bfloat162*)(xhi + o)     = __nv_bfloat162(hx, hy);
        *(__nv_bfloat162*)(xhi + o + 2) = __nv_bfloat162(hz, hw);
        *(__nv_bfloat162*)(xlo + o)     =
            __nv_bfloat162(__float2bfloat16(v.x - __bfloat162float(hx)),
                           __float2bfloat16(v.y - __bfloat162float(hy)));
        *(__nv_bfloat162*)(xlo + o + 2) =
            __nv_bfloat162(__float2bfloat16(v.z - __bfloat162float(hz)),
                           __float2bfloat16(v.w - __bfloat162float(hw)));
    }
    __syncthreads();

    const int j = tid & 31;
    const int chunk = tid >> 5;
    float acc = 0.0f;
    const int kbeg = chunk * 128;
    #pragma unroll 4
    for (int k = kbeg; k < kbeg + 128; k++)
        acc = fmaf(sx[k], Wwin[(size_t)k * 32 + j], acc);
    red[tid] = acc;
    __syncthreads();

    if (tid < 32) {
        float s = 0.0f;
        #pragma unroll
        for (int c = 0; c < 8; c++) s += red[c * 32 + tid];
        float wp = siluf_(s + bwin[tid]);
        float out;
        if (tid < 16) out = sigmoidf_(wp) * MAX_DIST + 0.5f;
        else          out = sigmoidf_(wp) * 9.5f + 0.5f;
        ws[(size_t)row * 32 + tid] = out;
    }
}

// ---------------------------------------------------------------------------
// Smem-tiled local-window attention with FUSED q/k LayerNorm.
// ---------------------------------------------------------------------------
#define TL      256
#define KROWS   (TL + 16)     // 272
#define KPITCH  274
#define OPITCH  257
#define SMEM_ATT (2 * 64 * KPITCH * 4)   // 140288 B

__global__ __launch_bounds__(256, 1) void attn_kernel(
    const float* __restrict__ q_g, const float* __restrict__ q_b,
    const float* __restrict__ k_g, const float* __restrict__ k_b)
{
    extern __shared__ float sm[];
    float* k_s = sm;
    float* v_s = sm + 64 * KPITCH;

    const int tid = threadIdx.x;
    const int l0  = blockIdx.x * TL;
    const int h   = blockIdx.y;
    const int b   = blockIdx.z;

    const size_t kvbase = (size_t)b * SEQ * (2 * EMB) + h * HDIM;
    for (int idx = tid; idx < KROWS * 16; idx += 256) {
        const int row = idx >> 4;
        const int c4  = idx & 15;
        const int pos = l0 - 8 + row;
        float4 kv4 = make_float4(0.f, 0.f, 0.f, 0.f);
        float4 vv4 = make_float4(0.f, 0.f, 0.f, 0.f);
        if (pos >= 0 && pos < SEQ) {
            const float* base = g_ykv + kvbase + (size_t)pos * (2 * EMB);
            kv4 = *(const float4*)(base + c4 * 4);
            vv4 = *(const float4*)(base + EMB + c4 * 4);
        }
        const int d0 = c4 * 4;
        k_s[(d0 + 0) * KPITCH + row] = kv4.x;
        k_s[(d0 + 1) * KPITCH + row] = kv4.y;
        k_s[(d0 + 2) * KPITCH + row] = kv4.z;
        k_s[(d0 + 3) * KPITCH + row] = kv4.w;
        v_s[(d0 + 0) * KPITCH + row] = vv4.x;
        v_s[(d0 + 1) * KPITCH + row] = vv4.y;
        v_s[(d0 + 2) * KPITCH + row] = vv4.z;
        v_s[(d0 + 3) * KPITCH + row] = vv4.w;
    }
    __syncthreads();

    // fused k LayerNorm over staged slab (valid rows only; OOB stays zero)
    for (int row = tid; row < KROWS; row += 256) {
        const int pos = l0 - 8 + row;
        if (pos >= 0 && pos < SEQ) {
            float s = 0.f, sq = 0.f;
            #pragma unroll 8
            for (int d = 0; d < 64; d++) {
                const float v = k_s[d * KPITCH + row];
                s += v; sq += v * v;
            }
            const float mu  = s * (1.0f / 64.0f);
            const float var = sq * (1.0f / 64.0f) - mu * mu;
            const float rs  = rsqrtf(var + 1e-5f);
            #pragma unroll 8
            for (int d = 0; d < 64; d++) {
                const float v = k_s[d * KPITCH + row];
                k_s[d * KPITCH + row] = (v - mu) * rs * k_g[d] + k_b[d];
            }
        }
    }
    __syncthreads();

    float sc0[WIN], sc1[WIN];
    const int t = tid;
    if (t < 128) {
        const int p0 = 2 * t;
        const int rg0 = b * SEQ + l0 + p0;
        const float* q0 = g_yq + (size_t)rg0 * EMB + h * HDIM;
        const float* q1 = q0 + EMB;

        float a0 = 0.f, v0a = 0.f, a1 = 0.f, v1a = 0.f;
        #pragma unroll 8
        for (int d = 0; d < 64; d++) {
            const float u0 = q0[d], u1 = q1[d];
            a0 += u0; v0a += u0 * u0;
            a1 += u1; v1a += u1 * u1;
        }
        const float mu0 = a0 * (1.0f / 64.0f);
        const float rs0 = rsqrtf(v0a * (1.0f / 64.0f) - mu0 * mu0 + 1e-5f);
        const float mu1 = a1 * (1.0f / 64.0f);
        const float rs1 = rsqrtf(v1a * (1.0f / 64.0f) - mu1 * mu1 + 1e-5f);

        #pragma unroll
        for (int w = 0; w < WIN; w++) { sc0[w] = 0.f; sc1[w] = 0.f; }

        for (int d = 0; d < 64; d++) {
            const float gd = q_g[d], bd = q_b[d];
            const float q0d = (q0[d] - mu0) * rs0 * gd + bd;
            const float q1d = (q1[d] - mu1) * rs1 * gd + bd;
            const float* kc = k_s + d * KPITCH + p0;
            float ka[18];
            #pragma unroll
            for (int j = 0; j < 9; j++) {
                float2 f2 = *(const float2*)(kc + 2 * j);
                ka[2 * j] = f2.x; ka[2 * j + 1] = f2.y;
            }
            #pragma unroll
            for (int w = 0; w < WIN; w++) {
                sc0[w] = fmaf(q0d, ka[w],     sc0[w]);
                sc1[w] = fmaf(q1d, ka[w + 1], sc1[w]);
            }
        }

        const float wd0 = g_ws[(size_t)rg0 * 32 + h];
        const float sh0 = g_ws[(size_t)rg0 * 32 + 16 + h];
        const float wd1 = g_ws[(size_t)(rg0 + 1) * 32 + h];
        const float sh1 = g_ws[(size_t)(rg0 + 1) * 32 + 16 + h];
        #pragma unroll
        for (int w = 0; w < WIN; w++) {
            const float rel = fabsf((float)w - 8.0f);
            sc0[w] = sc0[w] * SCALE - (1.0f - sigmoidf_((wd0 - rel) * sh0)) * MASK_PENALTY;
            sc1[w] = sc1[w] * SCALE - (1.0f - sigmoidf_((wd1 - rel) * sh1)) * MASK_PENALTY;
        }
        float m0 = sc0[0], m1 = sc1[0];
        #pragma unroll
        for (int w = 1; w < WIN; w++) { m0 = fmaxf(m0, sc0[w]); m1 = fmaxf(m1, sc1[w]); }
        float s0 = 0.f, s1 = 0.f;
        #pragma unroll
        for (int w = 0; w < WIN; w++) {
            sc0[w] = expf(sc0[w] - m0); s0 += sc0[w];
            sc1[w] = expf(sc1[w] - m1); s1 += sc1[w];
        }
        const float i0 = 1.0f / s0, i1 = 1.0f / s1;
        #pragma unroll
        for (int w = 0; w < WIN; w++) { sc0[w] *= i0; sc1[w] *= i1; }
    }
    __syncthreads();

    float* o_s = k_s;
    if (t < 128) {
        const int p0 = 2 * t;
        for (int d = 0; d < 64; d++) {
            const float* vc = v_s + d * KPITCH + p0;
            float va[18];
            #pragma unroll
            for (int j = 0; j < 9; j++) {
                float2 f2 = *(const float2*)(vc + 2 * j);
                va[2 * j] = f2.x; va[2 * j + 1] = f2.y;
            }
            float o0 = 0.f, o1 = 0.f;
            #pragma unroll
            for (int w = 0; w < WIN; w++) {
                o0 = fmaf(sc0[w], va[w],     o0);
                o1 = fmaf(sc1[w], va[w + 1], o1);
            }
            o_s[d * OPITCH + p0]     = o0;
            o_s[d * OPITCH + p0 + 1] = o1;
        }
    }
    __syncthreads();

    const int wid  = tid >> 5;
    const int lane = tid & 31;
    #pragma unroll
    for (int i = 0; i < 32; i++) {
        const int row = wid * 32 + i;
        const int rg  = b * SEQ + l0 + row;
        const float f0 = o_s[(2 * lane)     * OPITCH + row];
        const float f1 = o_s[(2 * lane + 1) * OPITCH + row];
        const __nv_bfloat16 h0 = __float2bfloat16(f0);
        const __nv_bfloat16 h1 = __float2bfloat16(f1);
        const size_t o = (size_t)rg * EMB + h * HDIM + 2 * lane;
        *(__nv_bfloat162*)(g_aohi + o) = __nv_bfloat162(h0, h1);
        *(__nv_bfloat162*)(g_aolo + o) =
            __nv_bfloat162(__float2bfloat16(f0 - __bfloat162float(h0)),
                           __float2bfloat16(f1 - __bfloat162float(h1)));
    }
}

// ---------------------------------------------------------------------------
// Launch — metadata order: x, Wq, Wkv, q_g, q_b, k_g, k_b, Wwin, bwin, Wout
// ---------------------------------------------------------------------------
extern "C" void kernel_launch(void* const* d_in, const int* in_sizes, int n_in,
                              void* d_out, int out_size)
{
    const float* x    = (const float*)d_in[0];
    const float* Wq   = (const float*)d_in[1];
    const float* Wkv  = (const float*)d_in[2];
    const float* q_g  = (const float*)d_in[3];
    const float* q_b  = (const float*)d_in[4];
    const float* k_g  = (const float*)d_in[5];
    const float* k_b  = (const float*)d_in[6];
    const float* Wwin = (const float*)d_in[7];
    const float* bwin = (const float*)d_in[8];
    const float* Wout = (const float*)d_in[9];
    float* out = (float*)d_out;

    float* yq;    cudaGetSymbolAddress((void**)&yq,    g_yq);
    float* ykv;   cudaGetSymbolAddress((void**)&ykv,   g_ykv);
    float* ws;    cudaGetSymbolAddress((void**)&ws,    g_ws);
    __nv_bfloat16 *xhi, *xlo, *aohi, *aolo, *wfh, *wfl, *woh, *wol;
    cudaGetSymbolAddress((void**)&xhi,  g_xhi);
    cudaGetSymbolAddress((void**)&xlo,  g_xlo);
    cudaGetSymbolAddress((void**)&aohi, g_aohi);
    cudaGetSymbolAddress((void**)&aolo, g_aolo);
    cudaGetSymbolAddress((void**)&wfh,  g_wfhi);
    cudaGetSymbolAddress((void**)&wfl,  g_wflo);
    cudaGetSymbolAddress((void**)&woh,  g_wothi);
    cudaGetSymbolAddress((void**)&wol,  g_wotlo);

    cudaFuncSetAttribute(gemm_mm_kernel, cudaFuncAttributeMaxDynamicSharedMemorySize, SMEM_GEMM);
    cudaFuncSetAttribute(attn_kernel,    cudaFuncAttributeMaxDynamicSharedMemorySize, SMEM_ATT);

    // 0) weight splits; win projection fused with x hi/lo split
    wsplit_kernel<<<dim3(EMB / 32,     KDIM / 32), 256>>>(Wq,   wfh,              wfl,              KDIM, EMB);
    wsplit_kernel<<<dim3(2 * EMB / 32, KDIM / 32), 256>>>(Wkv,  wfh + EMB * KDIM, wfl + EMB * KDIM, KDIM, 2 * EMB);
    wsplit_kernel<<<dim3(EMB / 32,     KDIM / 32), 256>>>(Wout, woh,              wol,              KDIM, EMB);
    win_kernel<<<ROWS, 256>>>(x, Wwin, bwin, ws, xhi, xlo);

    // 1) fused: [yq | ykv] = silu(x @ [Wq | Wkv])   (RAW; LN fused into attention)
    gemm_mm_kernel<<<dim3(3 * EMB / 128, ROWS / 128), 512, SMEM_GEMM>>>(
        xhi, xlo, wfh, wfl, yq, EMB, ykv, 2 * EMB, EMB);
    // 2) attention (fused q/k LN) -> split bf16 ao
    attn_kernel<<<dim3(SEQ / TL, HEADS, BATCH), 256, SMEM_ATT>>>(q_g, q_b, k_g, k_b);
    // 3) out = silu(ao @ Wout)
    gemm_mm_kernel<<<dim3(EMB / 128, ROWS / 128), 512, SMEM_GEMM>>>(
        aohi, aolo, woh, wol, out, EMB, out, EMB, EMB);
}

// round 15
// speedup vs baseline: 1.1348x; 1.0136x over previous
#include <cuda_runtime.h>
#include <cuda_bf16.h>
#include <math.h>
#include <stdint.h>

// ---------------------------------------------------------------------------
// Problem constants
// ---------------------------------------------------------------------------
#define BATCH 4
#define SEQ   2048
#define EMB   1024
#define HEADS 16
#define HDIM  64
#define WIN   17
#define ROWS  (BATCH * SEQ)          // 8192
#define SCALE 0.125f
#define MAX_DIST 8.0f
#define MASK_PENALTY 10000.0f
#define KDIM  1024

// ---------------------------------------------------------------------------
// Scratch (static device globals; no allocation allowed)
// ---------------------------------------------------------------------------
__device__ float g_yq [ROWS * EMB];        // silu(x@Wq), RAW (LN fused into attention)
__device__ float g_ykv[ROWS * 2 * EMB];    // silu(x@Wkv), RAW k + v
__device__ float g_ws [ROWS * 32];

__device__ __nv_bfloat16 g_xhi[ROWS * EMB];
__device__ __nv_bfloat16 g_xlo[ROWS * EMB];
__device__ __nv_bfloat16 g_aohi[ROWS * EMB];
__device__ __nv_bfloat16 g_aolo[ROWS * EMB];

__device__ __nv_bfloat16 g_wfhi[3 * EMB * KDIM];   // [Wq | Wkv]^T
__device__ __nv_bfloat16 g_wflo[3 * EMB * KDIM];
__device__ __nv_bfloat16 g_wothi[EMB * KDIM];      // Wout^T
__device__ __nv_bfloat16 g_wotlo[EMB * KDIM];

__device__ __forceinline__ float sigmoidf_(float x) { return 1.0f / (1.0f + expf(-x)); }
__device__ __forceinline__ float siluf_(float x)    { return x / (1.0f + expf(-x)); }

__device__ __forceinline__ uint32_t smem_u32(const void* p) {
    uint32_t a;
    asm("{ .reg .u64 t; cvta.to.shared.u64 t, %1; cvt.u32.u64 %0, t; }" : "=r"(a) : "l"(p));
    return a;
}

#define CP_ASYNC16(dst, src) \
    asm volatile("cp.async.cg.shared.global [%0], [%1], 16;" :: "r"(dst), "l"(src) : "memory")
#define CP_COMMIT() asm volatile("cp.async.commit_group;" ::: "memory")
#define CP_WAIT(n)  asm volatile("cp.async.wait_group %0;" :: "n"(n) : "memory")

__device__ __forceinline__ void ldmx4(uint32_t* r, uint32_t addr) {
    asm volatile("ldmatrix.sync.aligned.m8n8.x4.shared.b16 {%0,%1,%2,%3}, [%4];"
                 : "=r"(r[0]), "=r"(r[1]), "=r"(r[2]), "=r"(r[3]) : "r"(addr));
}
__device__ __forceinline__ void ldmx2(uint32_t* r, uint32_t addr) {
    asm volatile("ldmatrix.sync.aligned.m8n8.x2.shared.b16 {%0,%1}, [%2];"
                 : "=r"(r[0]), "=r"(r[1]) : "r"(addr));
}
__device__ __forceinline__ void mma16816(float* d, const uint32_t* a, const uint32_t* b) {
    asm volatile(
        "mma.sync.aligned.m16n8k16.row.col.f32.bf16.bf16.f32 "
        "{%0,%1,%2,%3}, {%4,%5,%6,%7}, {%8,%9}, {%0,%1,%2,%3};"
        : "+f"(d[0]), "+f"(d[1]), "+f"(d[2]), "+f"(d[3])
        : "r"(a[0]), "r"(a[1]), "r"(a[2]), "r"(a[3]), "r"(b[0]), "r"(b[1]));
}

// ---------------------------------------------------------------------------
// Split-bf16 tensor-core GEMM (R8 measured-best config): CTA 128x128x32,
// 512 threads, 16 warps (4x4), warp tile 32x32, ldmx4 A + ldmx2 B,
// 5-stage cp.async pipeline, next-stage load issued AFTER the MMA block.
// ---------------------------------------------------------------------------
#define BK        32
#define ROW_PITCH 80
#define MAT_BYTES (128 * ROW_PITCH)
#define STAGE_B   (4 * MAT_BYTES)        // 40960
#define NSTAGE    5
#define SMEM_GEMM (NSTAGE * STAGE_B)     // 204800

__device__ __forceinline__ void load_stage_mm(
    uint32_t stage, const __nv_bfloat16* Ah, const __nv_bfloat16* Al,
    const __nv_bfloat16* Bh, const __nv_bfloat16* Bl,
    int m0, int n0, int k0, int tid)
{
    #pragma unroll
    for (int j = 0; j < 4; j++) {
        const int g   = tid + j * 512;      // 0..2047
        const int mat = g >> 9;
        const int rem = g & 511;
        const int row = rem >> 2;
        const int c   = rem & 3;
        const uint32_t dst = stage + mat * MAT_BYTES + row * ROW_PITCH + c * 16;
        const __nv_bfloat16* src;
        if (mat == 0)      src = Ah + (size_t)(m0 + row) * KDIM + k0 + c * 8;
        else if (mat == 1) src = Al + (size_t)(m0 + row) * KDIM + k0 + c * 8;
        else if (mat == 2) src = Bh + (size_t)(n0 + row) * KDIM + k0 + c * 8;
        else               src = Bl + (size_t)(n0 + row) * KDIM + k0 + c * 8;
        CP_ASYNC16(dst, src);
    }
}

__global__ __launch_bounds__(512, 1) void gemm_mm_kernel(
    const __nv_bfloat16* __restrict__ Ah, const __nv_bfloat16* __restrict__ Al,
    const __nv_bfloat16* __restrict__ Bh, const __nv_bfloat16* __restrict__ Bl,
    float* __restrict__ C1, int ldc1, float* __restrict__ C2, int ldc2, int ncut)
{
    extern __shared__ char smem[];
    const uint32_t sb = smem_u32(smem);

    const int tid  = threadIdx.x;
    const int wid  = tid >> 5;       // 0..15
    const int lane = tid & 31;
    const int wm   = wid >> 2;       // 0..3 (32-row slab)
    const int wn   = wid & 3;        // 0..3 (32-col slab)
    const int m0   = blockIdx.y * 128;
    const int n0   = blockIdx.x * 128;

    float acc[2][4][4];
    #pragma unroll
    for (int f = 0; f < 2; f++)
        #pragma unroll
        for (int g = 0; g < 4; g++)
            #pragma unroll
            for (int c = 0; c < 4; c++) acc[f][g][c] = 0.0f;

    const int NCH = KDIM / BK;   // 32

    // prologue: fill NSTAGE-1 = 4 stages
    load_stage_mm(sb + 0 * STAGE_B, Ah, Al, Bh, Bl, m0, n0, 0 * BK, tid); CP_COMMIT();
    load_stage_mm(sb + 1 * STAGE_B, Ah, Al, Bh, Bl, m0, n0, 1 * BK, tid); CP_COMMIT();
    load_stage_mm(sb + 2 * STAGE_B, Ah, Al, Bh, Bl, m0, n0, 2 * BK, tid); CP_COMMIT();
    load_stage_mm(sb + 3 * STAGE_B, Ah, Al, Bh, Bl, m0, n0, 3 * BK, tid); CP_COMMIT();

    const uint32_t arow = (uint32_t)(lane & 15);
    const uint32_t achk = (uint32_t)(lane >> 4);
    const uint32_t brow = (uint32_t)(lane & 7);
    const uint32_t bchk = (uint32_t)((lane >> 3) & 1);

    for (int i = 0; i < NCH; i++) {
        // committed chunks so far: min(NCH-1, i+3); need chunk i complete
        const int pend = (NCH - 1 < i + 3 ? NCH - 1 : i + 3) - i;
        if (pend >= 3)      { CP_WAIT(3); }
        else if (pend == 2) { CP_WAIT(2); }
        else if (pend == 1) { CP_WAIT(1); }
        else                { CP_WAIT(0); }
        __syncthreads();

        const uint32_t stage = sb + (uint32_t)(i % NSTAGE) * STAGE_B;
        const uint32_t sAh = stage;
        const uint32_t sAl = stage + MAT_BYTES;
        const uint32_t sBh = stage + 2 * MAT_BYTES;
        const uint32_t sBl = stage + 3 * MAT_BYTES;

        #pragma unroll
        for (int s = 0; s < 2; s++) {
            uint32_t aH[2][4], aL[2][4], bH[4][2], bL[4][2];
            #pragma unroll
            for (int f = 0; f < 2; f++) {
                const uint32_t off = (uint32_t)(wm * 32 + f * 16 + arow) * ROW_PITCH
                                   + (2 * s + achk) * 16;
                ldmx4(aH[f], sAh + off);
                ldmx4(aL[f], sAl + off);
            }
            #pragma unroll
            for (int g = 0; g < 4; g++) {
                const uint32_t off = (uint32_t)(wn * 32 + g * 8 + brow) * ROW_PITCH
                                   + (2 * s + bchk) * 16;
                ldmx2(bH[g], sBh + off);
                ldmx2(bL[g], sBl + off);
            }
            #pragma unroll
            for (int f = 0; f < 2; f++)
                #pragma unroll
                for (int g = 0; g < 4; g++) mma16816(acc[f][g], aH[f], bH[g]);
            #pragma unroll
            for (int f = 0; f < 2; f++)
                #pragma unroll
                for (int g = 0; g < 4; g++) mma16816(acc[f][g], aH[f], bL[g]);
            #pragma unroll
            for (int f = 0; f < 2; f++)
                #pragma unroll
                for (int g = 0; g < 4; g++) mma16816(acc[f][g], aL[f], bH[g]);
        }

        if (i + 4 < NCH) {
            load_stage_mm(sb + (uint32_t)((i + 4) % NSTAGE) * STAGE_B,
                          Ah, Al, Bh, Bl, m0, n0, (i + 4) * BK, tid);
            CP_COMMIT();
        }
    }

    // epilogue: silu + fp32 store, routed by n0 (uniform per block)
    float* Cb; int ldc, nbase;
    if (n0 < ncut) { Cb = C1; ldc = ldc1; nbase = n0; }
    else           { Cb = C2; ldc = ldc2; nbase = n0 - ncut; }

    const int rlo  = m0 + wm * 32 + (lane >> 2);
    const int col0 = nbase + wn * 32 + 2 * (lane & 3);
    #pragma unroll
    for (int f = 0; f < 2; f++) {
        #pragma unroll
        for (int g = 0; g < 4; g++) {
            float2 v0, v1;
            v0.x = siluf_(acc[f][g][0]);
            v0.y = siluf_(acc[f][g][1]);
            v1.x = siluf_(acc[f][g][2]);
            v1.y = siluf_(acc[f][g][3]);
            const int col = col0 + g * 8;
            *(float2*)(Cb + (size_t)(rlo + f * 16)     * ldc + col) = v0;
            *(float2*)(Cb + (size_t)(rlo + f * 16 + 8) * ldc + col) = v1;
        }
    }
}

// ---------------------------------------------------------------------------
// W [K x N] fp32 -> W^T hi/lo bf16 [N x K]
// ---------------------------------------------------------------------------
__global__ __launch_bounds__(256) void wsplit_kernel(
    const float* __restrict__ W, __nv_bfloat16* __restrict__ Thi,
    __nv_bfloat16* __restrict__ Tlo, int K, int N)
{
    __shared__ float t[32][33];
    const int n0 = blockIdx.x * 32, k0 = blockIdx.y * 32;
    const int tx = threadIdx.x & 31, ty = threadIdx.x >> 5;
    #pragma unroll
    for (int j = 0; j < 4; j++)
        t[ty + 8 * j][tx] = W[(size_t)(k0 + ty + 8 * j) * N + n0 + tx];
    __syncthreads();
    #pragma unroll
    for (int j = 0; j < 4; j++) {
        const float v = t[tx][ty + 8 * j];
        const size_t o = (size_t)(n0 + ty + 8 * j) * K + k0 + tx;
        __nv_bfloat16 h = __float2bfloat16(v);
        Thi[o] = h;
        Tlo[o] = __float2bfloat16(v - __bfloat162float(h));
    }
}

// ---------------------------------------------------------------------------
// Win projection v2: tiled skinny GEMM. Block = 32 rows, 256 threads.
// k-chunks of 128 staged in smem (x chunk + Wwin chunk); Wwin read
// 256x total instead of 8192x. x hi/lo bf16 split fused into the x load.
// ---------------------------------------------------------------------------
#define WR 32
__global__ __launch_bounds__(256) void win_kernel(
    const float* __restrict__ x, const float* __restrict__ Wwin,
    const float* __restrict__ bwin, float* __restrict__ ws,
    __nv_bfloat16* __restrict__ xhi, __nv_bfloat16* __restrict__ xlo)
{
    __shared__ float sx[WR][128];     // 16 KB
    __shared__ float sw[128][32];     // 16 KB
    const int r0  = blockIdx.x * WR;
    const int tid = threadIdx.x;
    const int j   = tid & 31;
    const int rg  = tid >> 5;         // 0..7

    float acc[4] = {0.f, 0.f, 0.f, 0.f};

    for (int kc = 0; kc < 8; kc++) {
        __syncthreads();   // previous chunk fully consumed

        // x chunk: 32 rows x 32 float4 (+ fused hi/lo split)
        #pragma unroll
        for (int u = 0; u < 4; u++) {
            const int idx = tid + u * 256;        // 0..1023
            const int row = idx >> 5;
            const int c4  = idx & 31;
            const size_t go = (size_t)(r0 + row) * EMB + kc * 128 + c4 * 4;
            const float4 v = *(const float4*)(x + go);
            *(float4*)&sx[row][c4 * 4] = v;

            const __nv_bfloat16 hx = __float2bfloat16(v.x);
            const __nv_bfloat16 hy = __float2bfloat16(v.y);
            const __nv_bfloat16 hz = __float2bfloat16(v.z);
            const __nv_bfloat16 hw = __float2bfloat16(v.w);
            *(__nv_bfloat162*)(xhi + go)     = __nv_bfloat162(hx, hy);
            *(__nv_bfloat162*)(xhi + go + 2) = __nv_bfloat162(hz, hw);
            *(__nv_bfloat162*)(xlo + go)     =
                __nv_bfloat162(__float2bfloat16(v.x - __bfloat162float(hx)),
                               __float2bfloat16(v.y - __bfloat162float(hy)));
            *(__nv_bfloat162*)(xlo + go + 2) =
                __nv_bfloat162(__float2bfloat16(v.z - __bfloat162float(hz)),
                               __float2bfloat16(v.w - __bfloat162float(hw)));
        }
        // Wwin chunk: 128 k x 8 float4
        #pragma unroll
        for (int u = 0; u < 4; u++) {
            const int idx = tid + u * 256;        // 0..1023
            const int k   = idx >> 3;
            const int c4  = idx & 7;
            *(float4*)&sw[k][c4 * 4] =
                *(const float4*)(Wwin + (size_t)(kc * 128 + k) * 32 + c4 * 4);
        }
        __syncthreads();

        #pragma unroll 4
        for (int k = 0; k < 128; k++) {
            const float w = sw[k][j];
            #pragma unroll
            for (int i = 0; i < 4; i++)
                acc[i] = fmaf(sx[rg + 8 * i][k], w, acc[i]);
        }
    }

    const float bj = bwin[j];
    #pragma unroll
    for (int i = 0; i < 4; i++) {
        const int row = r0 + rg + 8 * i;
        const float wp = siluf_(acc[i] + bj);
        float out;
        if (j < 16) out = sigmoidf_(wp) * MAX_DIST + 0.5f;
        else        out = sigmoidf_(wp) * 9.5f + 0.5f;
        ws[(size_t)row * 32 + j] = out;
    }
}

// ---------------------------------------------------------------------------
// Smem-tiled local-window attention with FUSED q/k LayerNorm.
// ---------------------------------------------------------------------------
#define TL      256
#define KROWS   (TL + 16)     // 272
#define KPITCH  274
#define OPITCH  257
#define SMEM_ATT (2 * 64 * KPITCH * 4)   // 140288 B

__global__ __launch_bounds__(256, 1) void attn_kernel(
    const float* __restrict__ q_g, const float* __restrict__ q_b,
    const float* __restrict__ k_g, const float* __restrict__ k_b)
{
    extern __shared__ float sm[];
    float* k_s = sm;
    float* v_s = sm + 64 * KPITCH;

    const int tid = threadIdx.x;
    const int l0  = blockIdx.x * TL;
    const int h   = blockIdx.y;
    const int b   = blockIdx.z;

    const size_t kvbase = (size_t)b * SEQ * (2 * EMB) + h * HDIM;
    for (int idx = tid; idx < KROWS * 16; idx += 256) {
        const int row = idx >> 4;
        const int c4  = idx & 15;
        const int pos = l0 - 8 + row;
        float4 kv4 = make_float4(0.f, 0.f, 0.f, 0.f);
        float4 vv4 = make_float4(0.f, 0.f, 0.f, 0.f);
        if (pos >= 0 && pos < SEQ) {
            const float* base = g_ykv + kvbase + (size_t)pos * (2 * EMB);
            kv4 = *(const float4*)(base + c4 * 4);
            vv4 = *(const float4*)(base + EMB + c4 * 4);
        }
        const int d0 = c4 * 4;
        k_s[(d0 + 0) * KPITCH + row] = kv4.x;
        k_s[(d0 + 1) * KPITCH + row] = kv4.y;
        k_s[(d0 + 2) * KPITCH + row] = kv4.z;
        k_s[(d0 + 3) * KPITCH + row] = kv4.w;
        v_s[(d0 + 0) * KPITCH + row] = vv4.x;
        v_s[(d0 + 1) * KPITCH + row] = vv4.y;
        v_s[(d0 + 2) * KPITCH + row] = vv4.z;
        v_s[(d0 + 3) * KPITCH + row] = vv4.w;
    }
    __syncthreads();

    // fused k LayerNorm over staged slab (valid rows only; OOB stays zero)
    for (int row = tid; row < KROWS; row += 256) {
        const int pos = l0 - 8 + row;
        if (pos >= 0 && pos < SEQ) {
            float s = 0.f, sq = 0.f;
            #pragma unroll 8
            for (int d = 0; d < 64; d++) {
                const float v = k_s[d * KPITCH + row];
                s += v; sq += v * v;
            }
            const float mu  = s * (1.0f / 64.0f);
            const float var = sq * (1.0f / 64.0f) - mu * mu;
            const float rs  = rsqrtf(var + 1e-5f);
            #pragma unroll 8
            for (int d = 0; d < 64; d++) {
                const float v = k_s[d * KPITCH + row];
                k_s[d * KPITCH + row] = (v - mu) * rs * k_g[d] + k_b[d];
            }
        }
    }
    __syncthreads();

    float sc0[WIN], sc1[WIN];
    const int t = tid;
    if (t < 128) {
        const int p0 = 2 * t;
        const int rg0 = b * SEQ + l0 + p0;
        const float* q0 = g_yq + (size_t)rg0 * EMB + h * HDIM;
        const float* q1 = q0 + EMB;

        float a0 = 0.f, v0a = 0.f, a1 = 0.f, v1a = 0.f;
        #pragma unroll 8
        for (int d = 0; d < 64; d++) {
            const float u0 = q0[d], u1 = q1[d];
            a0 += u0; v0a += u0 * u0;
            a1 += u1; v1a += u1 * u1;
        }
        const float mu0 = a0 * (1.0f / 64.0f);
        const float rs0 = rsqrtf(v0a * (1.0f / 64.0f) - mu0 * mu0 + 1e-5f);
        const float mu1 = a1 * (1.0f / 64.0f);
        const float rs1 = rsqrtf(v1a * (1.0f / 64.0f) - mu1 * mu1 + 1e-5f);

        #pragma unroll
        for (int w = 0; w < WIN; w++) { sc0[w] = 0.f; sc1[w] = 0.f; }

        for (int d = 0; d < 64; d++) {
            const float gd = q_g[d], bd = q_b[d];
            const float q0d = (q0[d] - mu0) * rs0 * gd + bd;
            const float q1d = (q1[d] - mu1) * rs1 * gd + bd;
            const float* kc = k_s + d * KPITCH + p0;
            float ka[18];
            #pragma unroll
            for (int j = 0; j < 9; j++) {
                float2 f2 = *(const float2*)(kc + 2 * j);
                ka[2 * j] = f2.x; ka[2 * j + 1] = f2.y;
            }
            #pragma unroll
            for (int w = 0; w < WIN; w++) {
                sc0[w] = fmaf(q0d, ka[w],     sc0[w]);
                sc1[w] = fmaf(q1d, ka[w + 1], sc1[w]);
            }
        }

        const float wd0 = g_ws[(size_t)rg0 * 32 + h];
        const float sh0 = g_ws[(size_t)rg0 * 32 + 16 + h];
        const float wd1 = g_ws[(size_t)(rg0 + 1) * 32 + h];
        const float sh1 = g_ws[(size_t)(rg0 + 1) * 32 + 16 + h];
        #pragma unroll
        for (int w = 0; w < WIN; w++) {
            const float rel = fabsf((float)w - 8.0f);
            sc0[w] = sc0[w] * SCALE - (1.0f - sigmoidf_((wd0 - rel) * sh0)) * MASK_PENALTY;
            sc1[w] = sc1[w] * SCALE - (1.0f - sigmoidf_((wd1 - rel) * sh1)) * MASK_PENALTY;
        }
        float m0 = sc0[0], m1 = sc1[0];
        #pragma unroll
        for (int w = 1; w < WIN; w++) { m0 = fmaxf(m0, sc0[w]); m1 = fmaxf(m1, sc1[w]); }
        float s0 = 0.f, s1 = 0.f;
        #pragma unroll
        for (int w = 0; w < WIN; w++) {
            sc0[w] = expf(sc0[w] - m0); s0 += sc0[w];
            sc1[w] = expf(sc1[w] - m1); s1 += sc1[w];
        }
        const float i0 = 1.0f / s0, i1 = 1.0f / s1;
        #pragma unroll
        for (int w = 0; w < WIN; w++) { sc0[w] *= i0; sc1[w] *= i1; }
    }
    __syncthreads();

    float* o_s = k_s;
    if (t < 128) {
        const int p0 = 2 * t;
        for (int d = 0; d < 64; d++) {
            const float* vc = v_s + d * KPITCH + p0;
            float va[18];
            #pragma unroll
            for (int j = 0; j < 9; j++) {
                float2 f2 = *(const float2*)(vc + 2 * j);
                va[2 * j] = f2.x; va[2 * j + 1] = f2.y;
            }
            float o0 = 0.f, o1 = 0.f;
            #pragma unroll
            for (int w = 0; w < WIN; w++) {
                o0 = fmaf(sc0[w], va[w],     o0);
                o1 = fmaf(sc1[w], va[w + 1], o1);
            }
            o_s[d * OPITCH + p0]     = o0;
            o_s[d * OPITCH + p0 + 1] = o1;
        }
    }
    __syncthreads();

    const int wid  = tid >> 5;
    const int lane = tid & 31;
    #pragma unroll
    for (int i = 0; i < 32; i++) {
        const int row = wid * 32 + i;
        const int rg  = b * SEQ + l0 + row;
        const float f0 = o_s[(2 * lane)     * OPITCH + row];
        const float f1 = o_s[(2 * lane + 1) * OPITCH + row];
        const __nv_bfloat16 h0 = __float2bfloat16(f0);
        const __nv_bfloat16 h1 = __float2bfloat16(f1);
        const size_t o = (size_t)rg * EMB + h * HDIM + 2 * lane;
        *(__nv_bfloat162*)(g_aohi + o) = __nv_bfloat162(h0, h1);
        *(__nv_bfloat162*)(g_aolo + o) =
            __nv_bfloat162(__float2bfloat16(f0 - __bfloat162float(h0)),
                           __float2bfloat16(f1 - __bfloat162float(h1)));
    }
}

// ---------------------------------------------------------------------------
// Launch — metadata order: x, Wq, Wkv, q_g, q_b, k_g, k_b, Wwin, bwin, Wout
// ---------------------------------------------------------------------------
extern "C" void kernel_launch(void* const* d_in, const int* in_sizes, int n_in,
                              void* d_out, int out_size)
{
    const float* x    = (const float*)d_in[0];
    const float* Wq   = (const float*)d_in[1];
    const float* Wkv  = (const float*)d_in[2];
    const float* q_g  = (const float*)d_in[3];
    const float* q_b  = (const float*)d_in[4];
    const float* k_g  = (const float*)d_in[5];
    const float* k_b  = (const float*)d_in[6];
    const float* Wwin = (const float*)d_in[7];
    const float* bwin = (const float*)d_in[8];
    const float* Wout = (const float*)d_in[9];
    float* out = (float*)d_out;

    float* yq;    cudaGetSymbolAddress((void**)&yq,    g_yq);
    float* ykv;   cudaGetSymbolAddress((void**)&ykv,   g_ykv);
    float* ws;    cudaGetSymbolAddress((void**)&ws,    g_ws);
    __nv_bfloat16 *xhi, *xlo, *aohi, *aolo, *wfh, *wfl, *woh, *wol;
    cudaGetSymbolAddress((void**)&xhi,  g_xhi);
    cudaGetSymbolAddress((void**)&xlo,  g_xlo);
    cudaGetSymbolAddress((void**)&aohi, g_aohi);
    cudaGetSymbolAddress((void**)&aolo, g_aolo);
    cudaGetSymbolAddress((void**)&wfh,  g_wfhi);
    cudaGetSymbolAddress((void**)&wfl,  g_wflo);
    cudaGetSymbolAddress((void**)&woh,  g_wothi);
    cudaGetSymbolAddress((void**)&wol,  g_wotlo);

    cudaFuncSetAttribute(gemm_mm_kernel, cudaFuncAttributeMaxDynamicSharedMemorySize, SMEM_GEMM);
    cudaFuncSetAttribute(attn_kernel,    cudaFuncAttributeMaxDynamicSharedMemorySize, SMEM_ATT);

    // 0) weight splits; tiled win projection fused with x hi/lo split
    wsplit_kernel<<<dim3(EMB / 32,     KDIM / 32), 256>>>(Wq,   wfh,              wfl,              KDIM, EMB);
    wsplit_kernel<<<dim3(2 * EMB / 32, KDIM / 32), 256>>>(Wkv,  wfh + EMB * KDIM, wfl + EMB * KDIM, KDIM, 2 * EMB);
    wsplit_kernel<<<dim3(EMB / 32,     KDIM / 32), 256>>>(Wout, woh,              wol,              KDIM, EMB);
    win_kernel<<<ROWS / WR, 256>>>(x, Wwin, bwin, ws, xhi, xlo);

    // 1) fused: [yq | ykv] = silu(x @ [Wq | Wkv])   (RAW; LN fused into attention)
    gemm_mm_kernel<<<dim3(3 * EMB / 128, ROWS / 128), 512, SMEM_GEMM>>>(
        xhi, xlo, wfh, wfl, yq, EMB, ykv, 2 * EMB, EMB);
    // 2) attention (fused q/k LN) -> split bf16 ao
    attn_kernel<<<dim3(SEQ / TL, HEADS, BATCH), 256, SMEM_ATT>>>(q_g, q_b, k_g, k_b);
    // 3) out = silu(ao @ Wout)
    gemm_mm_kernel<<<dim3(EMB / 128, ROWS / 128), 512, SMEM_GEMM>>>(
        aohi, aolo, woh, wol, out, EMB, out, EMB, EMB);
}

// round 16
// speedup vs baseline: 1.1397x; 1.0043x over previous
#include <cuda_runtime.h>
#include <cuda_bf16.h>
#include <math.h>
#include <stdint.h>

// ---------------------------------------------------------------------------
// Problem constants
// ---------------------------------------------------------------------------
#define BATCH 4
#define SEQ   2048
#define EMB   1024
#define HEADS 16
#define HDIM  64
#define WIN   17
#define ROWS  (BATCH * SEQ)          // 8192
#define SCALE 0.125f
#define MAX_DIST 8.0f
#define MASK_PENALTY 10000.0f
#define KDIM  1024

// ---------------------------------------------------------------------------
// Scratch (static device globals; no allocation allowed)
// ---------------------------------------------------------------------------
__device__ float g_yq [ROWS * EMB];        // silu(x@Wq), RAW (LN fused into attention)
__device__ float g_ykv[ROWS * 2 * EMB];    // silu(x@Wkv), RAW k + v
__device__ float g_ws [ROWS * 32];

__device__ __nv_bfloat16 g_xhi[ROWS * EMB];
__device__ __nv_bfloat16 g_xlo[ROWS * EMB];
__device__ __nv_bfloat16 g_aohi[ROWS * EMB];
__device__ __nv_bfloat16 g_aolo[ROWS * EMB];

__device__ __nv_bfloat16 g_wfhi[3 * EMB * KDIM];   // [Wq | Wkv]^T
__device__ __nv_bfloat16 g_wflo[3 * EMB * KDIM];
__device__ __nv_bfloat16 g_wothi[EMB * KDIM];      // Wout^T
__device__ __nv_bfloat16 g_wotlo[EMB * KDIM];

__device__ __forceinline__ float sigmoidf_(float x) { return 1.0f / (1.0f + expf(-x)); }
__device__ __forceinline__ float siluf_(float x)    { return x / (1.0f + expf(-x)); }

__device__ __forceinline__ uint32_t smem_u32(const void* p) {
    uint32_t a;
    asm("{ .reg .u64 t; cvta.to.shared.u64 t, %1; cvt.u32.u64 %0, t; }" : "=r"(a) : "l"(p));
    return a;
}

#define CP_ASYNC16(dst, src) \
    asm volatile("cp.async.cg.shared.global [%0], [%1], 16;" :: "r"(dst), "l"(src) : "memory")
#define CP_COMMIT() asm volatile("cp.async.commit_group;" ::: "memory")
#define CP_WAIT(n)  asm volatile("cp.async.wait_group %0;" :: "n"(n) : "memory")

__device__ __forceinline__ void ldmx4(uint32_t* r, uint32_t addr) {
    asm volatile("ldmatrix.sync.aligned.m8n8.x4.shared.b16 {%0,%1,%2,%3}, [%4];"
                 : "=r"(r[0]), "=r"(r[1]), "=r"(r[2]), "=r"(r[3]) : "r"(addr));
}
__device__ __forceinline__ void ldmx2(uint32_t* r, uint32_t addr) {
    asm volatile("ldmatrix.sync.aligned.m8n8.x2.shared.b16 {%0,%1}, [%2];"
                 : "=r"(r[0]), "=r"(r[1]) : "r"(addr));
}
__device__ __forceinline__ void mma16816(float* d, const uint32_t* a, const uint32_t* b) {
    asm volatile(
        "mma.sync.aligned.m16n8k16.row.col.f32.bf16.bf16.f32 "
        "{%0,%1,%2,%3}, {%4,%5,%6,%7}, {%8,%9}, {%0,%1,%2,%3};"
        : "+f"(d[0]), "+f"(d[1]), "+f"(d[2]), "+f"(d[3])
        : "r"(a[0]), "r"(a[1]), "r"(a[2]), "r"(a[3]), "r"(b[0]), "r"(b[1]));
}

// ---------------------------------------------------------------------------
// Split-bf16 tensor-core GEMM (R8 measured-best config): CTA 128x128x32,
// 512 threads, 16 warps (4x4), warp tile 32x32, ldmx4 A + ldmx2 B,
// 5-stage cp.async pipeline, next-stage load issued AFTER the MMA block.
// ---------------------------------------------------------------------------
#define BK        32
#define ROW_PITCH 80
#define MAT_BYTES (128 * ROW_PITCH)
#define STAGE_B   (4 * MAT_BYTES)        // 40960
#define NSTAGE    5
#define SMEM_GEMM (NSTAGE * STAGE_B)     // 204800

__device__ __forceinline__ void load_stage_mm(
    uint32_t stage, const __nv_bfloat16* Ah, const __nv_bfloat16* Al,
    const __nv_bfloat16* Bh, const __nv_bfloat16* Bl,
    int m0, int n0, int k0, int tid)
{
    #pragma unroll
    for (int j = 0; j < 4; j++) {
        const int g   = tid + j * 512;      // 0..2047
        const int mat = g >> 9;
        const int rem = g & 511;
        const int row = rem >> 2;
        const int c   = rem & 3;
        const uint32_t dst = stage + mat * MAT_BYTES + row * ROW_PITCH + c * 16;
        const __nv_bfloat16* src;
        if (mat == 0)      src = Ah + (size_t)(m0 + row) * KDIM + k0 + c * 8;
        else if (mat == 1) src = Al + (size_t)(m0 + row) * KDIM + k0 + c * 8;
        else if (mat == 2) src = Bh + (size_t)(n0 + row) * KDIM + k0 + c * 8;
        else               src = Bl + (size_t)(n0 + row) * KDIM + k0 + c * 8;
        CP_ASYNC16(dst, src);
    }
}

__global__ __launch_bounds__(512, 1) void gemm_mm_kernel(
    const __nv_bfloat16* __restrict__ Ah, const __nv_bfloat16* __restrict__ Al,
    const __nv_bfloat16* __restrict__ Bh, const __nv_bfloat16* __restrict__ Bl,
    float* __restrict__ C1, int ldc1, float* __restrict__ C2, int ldc2, int ncut)
{
    extern __shared__ char smem[];
    const uint32_t sb = smem_u32(smem);

    const int tid  = threadIdx.x;
    const int wid  = tid >> 5;       // 0..15
    const int lane = tid & 31;
    const int wm   = wid >> 2;       // 0..3 (32-row slab)
    const int wn   = wid & 3;        // 0..3 (32-col slab)
    const int m0   = blockIdx.y * 128;
    const int n0   = blockIdx.x * 128;

    float acc[2][4][4];
    #pragma unroll
    for (int f = 0; f < 2; f++)
        #pragma unroll
        for (int g = 0; g < 4; g++)
            #pragma unroll
            for (int c = 0; c < 4; c++) acc[f][g][c] = 0.0f;

    const int NCH = KDIM / BK;   // 32

    // prologue: fill NSTAGE-1 = 4 stages
    load_stage_mm(sb + 0 * STAGE_B, Ah, Al, Bh, Bl, m0, n0, 0 * BK, tid); CP_COMMIT();
    load_stage_mm(sb + 1 * STAGE_B, Ah, Al, Bh, Bl, m0, n0, 1 * BK, tid); CP_COMMIT();
    load_stage_mm(sb + 2 * STAGE_B, Ah, Al, Bh, Bl, m0, n0, 2 * BK, tid); CP_COMMIT();
    load_stage_mm(sb + 3 * STAGE_B, Ah, Al, Bh, Bl, m0, n0, 3 * BK, tid); CP_COMMIT();

    const uint32_t arow = (uint32_t)(lane & 15);
    const uint32_t achk = (uint32_t)(lane >> 4);
    const uint32_t brow = (uint32_t)(lane & 7);
    const uint32_t bchk = (uint32_t)((lane >> 3) & 1);

    for (int i = 0; i < NCH; i++) {
        // committed chunks so far: min(NCH-1, i+3); need chunk i complete
        const int pend = (NCH - 1 < i + 3 ? NCH - 1 : i + 3) - i;
        if (pend >= 3)      { CP_WAIT(3); }
        else if (pend == 2) { CP_WAIT(2); }
        else if (pend == 1) { CP_WAIT(1); }
        else                { CP_WAIT(0); }
        __syncthreads();

        const uint32_t stage = sb + (uint32_t)(i % NSTAGE) * STAGE_B;
        const uint32_t sAh = stage;
        const uint32_t sAl = stage + MAT_BYTES;
        const uint32_t sBh = stage + 2 * MAT_BYTES;
        const uint32_t sBl = stage + 3 * MAT_BYTES;

        #pragma unroll
        for (int s = 0; s < 2; s++) {
            uint32_t aH[2][4], aL[2][4], bH[4][2], bL[4][2];
            #pragma unroll
            for (int f = 0; f < 2; f++) {
                const uint32_t off = (uint32_t)(wm * 32 + f * 16 + arow) * ROW_PITCH
                                   + (2 * s + achk) * 16;
                ldmx4(aH[f], sAh + off);
                ldmx4(aL[f], sAl + off);
            }
            #pragma unroll
            for (int g = 0; g < 4; g++) {
                const uint32_t off = (uint32_t)(wn * 32 + g * 8 + brow) * ROW_PITCH
                                   + (2 * s + bchk) * 16;
                ldmx2(bH[g], sBh + off);
                ldmx2(bL[g], sBl + off);
            }
            #pragma unroll
            for (int f = 0; f < 2; f++)
                #pragma unroll
                for (int g = 0; g < 4; g++) mma16816(acc[f][g], aH[f], bH[g]);
            #pragma unroll
            for (int f = 0; f < 2; f++)
                #pragma unroll
                for (int g = 0; g < 4; g++) mma16816(acc[f][g], aH[f], bL[g]);
            #pragma unroll
            for (int f = 0; f < 2; f++)
                #pragma unroll
                for (int g = 0; g < 4; g++) mma16816(acc[f][g], aL[f], bH[g]);
        }

        if (i + 4 < NCH) {
            load_stage_mm(sb + (uint32_t)((i + 4) % NSTAGE) * STAGE_B,
                          Ah, Al, Bh, Bl, m0, n0, (i + 4) * BK, tid);
            CP_COMMIT();
        }
    }

    // epilogue: silu + fp32 store, routed by n0 (uniform per block)
    float* Cb; int ldc, nbase;
    if (n0 < ncut) { Cb = C1; ldc = ldc1; nbase = n0; }
    else           { Cb = C2; ldc = ldc2; nbase = n0 - ncut; }

    const int rlo  = m0 + wm * 32 + (lane >> 2);
    const int col0 = nbase + wn * 32 + 2 * (lane & 3);
    #pragma unroll
    for (int f = 0; f < 2; f++) {
        #pragma unroll
        for (int g = 0; g < 4; g++) {
            float2 v0, v1;
            v0.x = siluf_(acc[f][g][0]);
            v0.y = siluf_(acc[f][g][1]);
            v1.x = siluf_(acc[f][g][2]);
            v1.y = siluf_(acc[f][g][3]);
            const int col = col0 + g * 8;
            *(float2*)(Cb + (size_t)(rlo + f * 16)     * ldc + col) = v0;
            *(float2*)(Cb + (size_t)(rlo + f * 16 + 8) * ldc + col) = v1;
        }
    }
}

// ---------------------------------------------------------------------------
// W [K x N] fp32 -> W^T hi/lo bf16 [N x K]
// ---------------------------------------------------------------------------
__global__ __launch_bounds__(256) void wsplit_kernel(
    const float* __restrict__ W, __nv_bfloat16* __restrict__ Thi,
    __nv_bfloat16* __restrict__ Tlo, int K, int N)
{
    __shared__ float t[32][33];
    const int n0 = blockIdx.x * 32, k0 = blockIdx.y * 32;
    const int tx = threadIdx.x & 31, ty = threadIdx.x >> 5;
    #pragma unroll
    for (int j = 0; j < 4; j++)
        t[ty + 8 * j][tx] = W[(size_t)(k0 + ty + 8 * j) * N + n0 + tx];
    __syncthreads();
    #pragma unroll
    for (int j = 0; j < 4; j++) {
        const float v = t[tx][ty + 8 * j];
        const size_t o = (size_t)(n0 + ty + 8 * j) * K + k0 + tx;
        __nv_bfloat16 h = __float2bfloat16(v);
        Thi[o] = h;
        Tlo[o] = __float2bfloat16(v - __bfloat162float(h));
    }
}

// ---------------------------------------------------------------------------
// Win projection v3: tiled skinny GEMM, WR=16 rows/block -> grid 512
// (R15 measured occ=22% at grid 256; double block count for latency hiding).
// Wwin chunk staged in smem; x hi/lo bf16 split fused into the x load.
// ---------------------------------------------------------------------------
#define WR 16
__global__ __launch_bounds__(256) void win_kernel(
    const float* __restrict__ x, const float* __restrict__ Wwin,
    const float* __restrict__ bwin, float* __restrict__ ws,
    __nv_bfloat16* __restrict__ xhi, __nv_bfloat16* __restrict__ xlo)
{
    __shared__ float sx[WR][128];     // 8 KB
    __shared__ float sw[128][32];     // 16 KB
    const int r0  = blockIdx.x * WR;
    const int tid = threadIdx.x;
    const int j   = tid & 31;
    const int rg  = tid >> 5;         // 0..7

    float acc[2] = {0.f, 0.f};

    for (int kc = 0; kc < 8; kc++) {
        __syncthreads();   // previous chunk fully consumed

        // x chunk: 16 rows x 32 float4 (+ fused hi/lo split)
        #pragma unroll
        for (int u = 0; u < 2; u++) {
            const int idx = tid + u * 256;        // 0..511
            const int row = idx >> 5;             // 0..15
            const int c4  = idx & 31;
            const size_t go = (size_t)(r0 + row) * EMB + kc * 128 + c4 * 4;
            const float4 v = *(const float4*)(x + go);
            *(float4*)&sx[row][c4 * 4] = v;

            const __nv_bfloat16 hx = __float2bfloat16(v.x);
            const __nv_bfloat16 hy = __float2bfloat16(v.y);
            const __nv_bfloat16 hz = __float2bfloat16(v.z);
            const __nv_bfloat16 hw = __float2bfloat16(v.w);
            *(__nv_bfloat162*)(xhi + go)     = __nv_bfloat162(hx, hy);
            *(__nv_bfloat162*)(xhi + go + 2) = __nv_bfloat162(hz, hw);
            *(__nv_bfloat162*)(xlo + go)     =
                __nv_bfloat162(__float2bfloat16(v.x - __bfloat162float(hx)),
                               __float2bfloat16(v.y - __bfloat162float(hy)));
            *(__nv_bfloat162*)(xlo + go + 2) =
                __nv_bfloat162(__float2bfloat16(v.z - __bfloat162float(hz)),
                               __float2bfloat16(v.w - __bfloat162float(hw)));
        }
        // Wwin chunk: 128 k x 8 float4
        #pragma unroll
        for (int u = 0; u < 4; u++) {
            const int idx = tid + u * 256;        // 0..1023
            const int k   = idx >> 3;
            const int c4  = idx & 7;
            *(float4*)&sw[k][c4 * 4] =
                *(const float4*)(Wwin + (size_t)(kc * 128 + k) * 32 + c4 * 4);
        }
        __syncthreads();

        #pragma unroll 4
        for (int k = 0; k < 128; k++) {
            const float w = sw[k][j];
            acc[0] = fmaf(sx[rg][k],     w, acc[0]);
            acc[1] = fmaf(sx[rg + 8][k], w, acc[1]);
        }
    }

    const float bj = bwin[j];
    #pragma unroll
    for (int i = 0; i < 2; i++) {
        const int row = r0 + rg + 8 * i;
        const float wp = siluf_(acc[i] + bj);
        float out;
        if (j < 16) out = sigmoidf_(wp) * MAX_DIST + 0.5f;
        else        out = sigmoidf_(wp) * 9.5f + 0.5f;
        ws[(size_t)row * 32 + j] = out;
    }
}

// ---------------------------------------------------------------------------
// Smem-tiled local-window attention with FUSED q/k LayerNorm.
// ---------------------------------------------------------------------------
#define TL      256
#define KROWS   (TL + 16)     // 272
#define KPITCH  274
#define OPITCH  257
#define SMEM_ATT (2 * 64 * KPITCH * 4)   // 140288 B

__global__ __launch_bounds__(256, 1) void attn_kernel(
    const float* __restrict__ q_g, const float* __restrict__ q_b,
    const float* __restrict__ k_g, const float* __restrict__ k_b)
{
    extern __shared__ float sm[];
    float* k_s = sm;
    float* v_s = sm + 64 * KPITCH;

    const int tid = threadIdx.x;
    const int l0  = blockIdx.x * TL;
    const int h   = blockIdx.y;
    const int b   = blockIdx.z;

    const size_t kvbase = (size_t)b * SEQ * (2 * EMB) + h * HDIM;
    for (int idx = tid; idx < KROWS * 16; idx += 256) {
        const int row = idx >> 4;
        const int c4  = idx & 15;
        const int pos = l0 - 8 + row;
        float4 kv4 = make_float4(0.f, 0.f, 0.f, 0.f);
        float4 vv4 = make_float4(0.f, 0.f, 0.f, 0.f);
        if (pos >= 0 && pos < SEQ) {
            const float* base = g_ykv + kvbase + (size_t)pos * (2 * EMB);
            kv4 = *(const float4*)(base + c4 * 4);
            vv4 = *(const float4*)(base + EMB + c4 * 4);
        }
        const int d0 = c4 * 4;
        k_s[(d0 + 0) * KPITCH + row] = kv4.x;
        k_s[(d0 + 1) * KPITCH + row] = kv4.y;
        k_s[(d0 + 2) * KPITCH + row] = kv4.z;
        k_s[(d0 + 3) * KPITCH + row] = kv4.w;
        v_s[(d0 + 0) * KPITCH + row] = vv4.x;
        v_s[(d0 + 1) * KPITCH + row] = vv4.y;
        v_s[(d0 + 2) * KPITCH + row] = vv4.z;
        v_s[(d0 + 3) * KPITCH + row] = vv4.w;
    }
    __syncthreads();

    // fused k LayerNorm over staged slab (valid rows only; OOB stays zero)
    for (int row = tid; row < KROWS; row += 256) {
        const int pos = l0 - 8 + row;
        if (pos >= 0 && pos < SEQ) {
            float s = 0.f, sq = 0.f;
            #pragma unroll 8
            for (int d = 0; d < 64; d++) {
                const float v = k_s[d * KPITCH + row];
                s += v; sq += v * v;
            }
            const float mu  = s * (1.0f / 64.0f);
            const float var = sq * (1.0f / 64.0f) - mu * mu;
            const float rs  = rsqrtf(var + 1e-5f);
            #pragma unroll 8
            for (int d = 0; d < 64; d++) {
                const float v = k_s[d * KPITCH + row];
                k_s[d * KPITCH + row] = (v - mu) * rs * k_g[d] + k_b[d];
            }
        }
    }
    __syncthreads();

    float sc0[WIN], sc1[WIN];
    const int t = tid;
    if (t < 128) {
        const int p0 = 2 * t;
        const int rg0 = b * SEQ + l0 + p0;
        const float* q0 = g_yq + (size_t)rg0 * EMB + h * HDIM;
        const float* q1 = q0 + EMB;

        float a0 = 0.f, v0a = 0.f, a1 = 0.f, v1a = 0.f;
        #pragma unroll 8
        for (int d = 0; d < 64; d++) {
            const float u0 = q0[d], u1 = q1[d];
            a0 += u0; v0a += u0 * u0;
            a1 += u1; v1a += u1 * u1;
        }
        const float mu0 = a0 * (1.0f / 64.0f);
        const float rs0 = rsqrtf(v0a * (1.0f / 64.0f) - mu0 * mu0 + 1e-5f);
        const float mu1 = a1 * (1.0f / 64.0f);
        const float rs1 = rsqrtf(v1a * (1.0f / 64.0f) - mu1 * mu1 + 1e-5f);

        #pragma unroll
        for (int w = 0; w < WIN; w++) { sc0[w] = 0.f; sc1[w] = 0.f; }

        for (int d = 0; d < 64; d++) {
            const float gd = q_g[d], bd = q_b[d];
            const float q0d = (q0[d] - mu0) * rs0 * gd + bd;
            const float q1d = (q1[d] - mu1) * rs1 * gd + bd;
            const float* kc = k_s + d * KPITCH + p0;
            float ka[18];
            #pragma unroll
            for (int j = 0; j < 9; j++) {
                float2 f2 = *(const float2*)(kc + 2 * j);
                ka[2 * j] = f2.x; ka[2 * j + 1] = f2.y;
            }
            #pragma unroll
            for (int w = 0; w < WIN; w++) {
                sc0[w] = fmaf(q0d, ka[w],     sc0[w]);
                sc1[w] = fmaf(q1d, ka[w + 1], sc1[w]);
            }
        }

        const float wd0 = g_ws[(size_t)rg0 * 32 + h];
        const float sh0 = g_ws[(size_t)rg0 * 32 + 16 + h];
        const float wd1 = g_ws[(size_t)(rg0 + 1) * 32 + h];
        const float sh1 = g_ws[(size_t)(rg0 + 1) * 32 + 16 + h];
        #pragma unroll
        for (int w = 0; w < WIN; w++) {
            const float rel = fabsf((float)w - 8.0f);
            sc0[w] = sc0[w] * SCALE - (1.0f - sigmoidf_((wd0 - rel) * sh0)) * MASK_PENALTY;
            sc1[w] = sc1[w] * SCALE - (1.0f - sigmoidf_((wd1 - rel) * sh1)) * MASK_PENALTY;
        }
        float m0 = sc0[0], m1 = sc1[0];
        #pragma unroll
        for (int w = 1; w < WIN; w++) { m0 = fmaxf(m0, sc0[w]); m1 = fmaxf(m1, sc1[w]); }
        float s0 = 0.f, s1 = 0.f;
        #pragma unroll
        for (int w = 0; w < WIN; w++) {
            sc0[w] = expf(sc0[w] - m0); s0 += sc0[w];
            sc1[w] = expf(sc1[w] - m1); s1 += sc1[w];
        }
        const float i0 = 1.0f / s0, i1 = 1.0f / s1;
        #pragma unroll
        for (int w = 0; w < WIN; w++) { sc0[w] *= i0; sc1[w] *= i1; }
    }
    __syncthreads();

    float* o_s = k_s;
    if (t < 128) {
        const int p0 = 2 * t;
        for (int d = 0; d < 64; d++) {
            const float* vc = v_s + d * KPITCH + p0;
            float va[18];
            #pragma unroll
            for (int j = 0; j < 9; j++) {
                float2 f2 = *(const float2*)(vc + 2 * j);
                va[2 * j] = f2.x; va[2 * j + 1] = f2.y;
            }
            float o0 = 0.f, o1 = 0.f;
            #pragma unroll
            for (int w = 0; w < WIN; w++) {
                o0 = fmaf(sc0[w], va[w],     o0);
                o1 = fmaf(sc1[w], va[w + 1], o1);
            }
            o_s[d * OPITCH + p0]     = o0;
            o_s[d * OPITCH + p0 + 1] = o1;
        }
    }
    __syncthreads();

    const int wid  = tid >> 5;
    const int lane = tid & 31;
    #pragma unroll
    for (int i = 0; i < 32; i++) {
        const int row = wid * 32 + i;
        const int rg  = b * SEQ + l0 + row;
        const float f0 = o_s[(2 * lane)     * OPITCH + row];
        const float f1 = o_s[(2 * lane + 1) * OPITCH + row];
        const __nv_bfloat16 h0 = __float2bfloat16(f0);
        const __nv_bfloat16 h1 = __float2bfloat16(f1);
        const size_t o = (size_t)rg * EMB + h * HDIM + 2 * lane;
        *(__nv_bfloat162*)(g_aohi + o) = __nv_bfloat162(h0, h1);
        *(__nv_bfloat162*)(g_aolo + o) =
            __nv_bfloat162(__float2bfloat16(f0 - __bfloat162float(h0)),
                           __float2bfloat16(f1 - __bfloat162float(h1)));
    }
}

// ---------------------------------------------------------------------------
// Launch — metadata order: x, Wq, Wkv, q_g, q_b, k_g, k_b, Wwin, bwin, Wout
// ---------------------------------------------------------------------------
extern "C" void kernel_launch(void* const* d_in, const int* in_sizes, int n_in,
                              void* d_out, int out_size)
{
    const float* x    = (const float*)d_in[0];
    const float* Wq   = (const float*)d_in[1];
    const float* Wkv  = (const float*)d_in[2];
    const float* q_g  = (const float*)d_in[3];
    const float* q_b  = (const float*)d_in[4];
    const float* k_g  = (const float*)d_in[5];
    const float* k_b  = (const float*)d_in[6];
    const float* Wwin = (const float*)d_in[7];
    const float* bwin = (const float*)d_in[8];
    const float* Wout = (const float*)d_in[9];
    float* out = (float*)d_out;

    float* yq;    cudaGetSymbolAddress((void**)&yq,    g_yq);
    float* ykv;   cudaGetSymbolAddress((void**)&ykv,   g_ykv);
    float* ws;    cudaGetSymbolAddress((void**)&ws,    g_ws);
    __nv_bfloat16 *xhi, *xlo, *aohi, *aolo, *wfh, *wfl, *woh, *wol;
    cudaGetSymbolAddress((void**)&xhi,  g_xhi);
    cudaGetSymbolAddress((void**)&xlo,  g_xlo);
    cudaGetSymbolAddress((void**)&aohi, g_aohi);
    cudaGetSymbolAddress((void**)&aolo, g_aolo);
    cudaGetSymbolAddress((void**)&wfh,  g_wfhi);
    cudaGetSymbolAddress((void**)&wfl,  g_wflo);
    cudaGetSymbolAddress((void**)&woh,  g_wothi);
    cudaGetSymbolAddress((void**)&wol,  g_wotlo);

    cudaFuncSetAttribute(gemm_mm_kernel, cudaFuncAttributeMaxDynamicSharedMemorySize, SMEM_GEMM);
    cudaFuncSetAttribute(attn_kernel,    cudaFuncAttributeMaxDynamicSharedMemorySize, SMEM_ATT);

    // 0) weight splits; tiled win projection fused with x hi/lo split
    wsplit_kernel<<<dim3(EMB / 32,     KDIM / 32), 256>>>(Wq,   wfh,              wfl,              KDIM, EMB);
    wsplit_kernel<<<dim3(2 * EMB / 32, KDIM / 32), 256>>>(Wkv,  wfh + EMB * KDIM, wfl + EMB * KDIM, KDIM, 2 * EMB);
    wsplit_kernel<<<dim3(EMB / 32,     KDIM / 32), 256>>>(Wout, woh,              wol,              KDIM, EMB);
    win_kernel<<<ROWS / WR, 256>>>(x, Wwin, bwin, ws, xhi, xlo);

    // 1) fused: [yq | ykv] = silu(x @ [Wq | Wkv])   (RAW; LN fused into attention)
    gemm_mm_kernel<<<dim3(3 * EMB / 128, ROWS / 128), 512, SMEM_GEMM>>>(
        xhi, xlo, wfh, wfl, yq, EMB, ykv, 2 * EMB, EMB);
    // 2) attention (fused q/k LN) -> split bf16 ao
    attn_kernel<<<dim3(SEQ / TL, HEADS, BATCH), 256, SMEM_ATT>>>(q_g, q_b, k_g, k_b);
    // 3) out = silu(ao @ Wout)
    gemm_mm_kernel<<<dim3(EMB / 128, ROWS / 128), 512, SMEM_GEMM>>>(
        aohi, aolo, woh, wol, out, EMB, out, EMB, EMB);
}